// round 4
// baseline (speedup 1.0000x reference)
#include <cuda_runtime.h>
#include <cfloat>
#include <cstdint>
#include <math.h>

#define BB 4
#define NN 8192
#define KNN 10
#define MTOT (BB*NN)
#define LDD 129   // padded row stride of distance staging tile

// ---------------- scratch (device globals; no allocation allowed) ----------------
__device__ float    g_x0p[MTOT*8];      // [t,t,0,0] padded to 8 channels
__device__ float    g_x1[MTOT*64];
__device__ float    g_x2[MTOT*64];
__device__ float    g_x3[MTOT*64];
__device__ float    g_u[MTOT*64];
__device__ float    g_v[MTOT*64];
__device__ float    g_nrm[MTOT];
__device__ int      g_knn[MTOT*KNN];
__device__ unsigned g_x5max[BB*1024];   // ordered-uint encoded float max
__device__ float    g_bias7[BB*256];
__device__ float    g_ya[MTOT*256];
__device__ float    g_yb[MTOT*256];

// ---------------- helpers ----------------
__device__ __forceinline__ float prelu_f(float v, float a){ return v >= 0.f ? v : a*v; }

__device__ __forceinline__ unsigned enc_f(float f){
    unsigned u = __float_as_uint(f);
    return (u & 0x80000000u) ? ~u : (u | 0x80000000u);
}
__device__ __forceinline__ float dec_f(unsigned u){
    return (u & 0x80000000u) ? __uint_as_float(u & 0x7fffffffu) : __uint_as_float(~u);
}

// ---- packed fp32x2 primitives (Blackwell FFMA2; exact rn per lane) ----
__device__ __forceinline__ unsigned long long dup_f(float x){
    unsigned long long r;
    asm("mov.b64 %0, {%1, %1};" : "=l"(r) : "f"(x));
    return r;
}
__device__ __forceinline__ void fma2(unsigned long long &acc, unsigned long long a, unsigned long long b){
    asm("fma.rn.f32x2 %0, %1, %2, %0;" : "+l"(acc) : "l"(a), "l"(b));
}
__device__ __forceinline__ float2 unpack2(unsigned long long v){
    float lo, hi;
    asm("mov.b64 {%0, %1}, %2;" : "=f"(lo), "=f"(hi) : "l"(v));
    return make_float2(lo, hi);
}

// register top-10 insertion (ascending; ties keep earlier/lower index)
__device__ __forceinline__ void topk_insert(float (&dist)[KNN], int (&idx)[KNN], float d, int j){
    if (d < dist[KNN-1]){
        float cd = d; int cj = j;
#pragma unroll
        for (int p = 0; p < KNN; p++){
            if (cd < dist[p]){
                float td = dist[p]; int tj = idx[p];
                dist[p] = cd; idx[p] = cj;
                cd = td; cj = tj;
            }
        }
    }
}

// ---------------- build x0p = [t,t,0,0] padded to 8 ----------------
__global__ __launch_bounds__(256) void build_x0p_kernel(const float* __restrict__ t){
    int i = blockIdx.x*256 + threadIdx.x;
    float t0 = t[i*3+0], t1 = t[i*3+1], t2 = t[i*3+2];
    float4* o = (float4*)(g_x0p + (size_t)i*8);
    o[0] = make_float4(t0, t1, t2, t0);
    o[1] = make_float4(t1, t2, 0.f, 0.f);
}

// ---------------- row squared norms ----------------
template<int KCH>
__global__ __launch_bounds__(256) void norms_kernel(const float* __restrict__ x, float* __restrict__ nrm){
    int r = blockIdx.x*256 + threadIdx.x;
    const float* xr = x + (size_t)r*KCH;
    float s = 0.f;
#pragma unroll
    for (int k = 0; k < KCH; k++) s = fmaf(xr[k], xr[k], s);
    nrm[r] = s;
}

// ---------------- kNN: FFMA2-tiled distances + in-register top-10 ----------------
// 128 threads, 128 queries x 128-candidate sweep. Microtile 8q x 16c per thread.
// Queries packed as natural f32x2 pairs from k-major smem; candidates reg-dup'd.
// Topk: 1 thread per query scans the staged distance tile (ascending index, stable).
template<int KCH>
__global__ __launch_bounds__(128, 1) void knn_tile_kernel(
    const float* __restrict__ x, const float* __restrict__ nrm, int* __restrict__ knnout)
{
    extern __shared__ float sm[];
    float* Qs = sm;                    // KCH*128  (k-major)
    float* Cs = Qs + KCH*128;          // KCH*128
    float* qn = Cs + KCH*128;          // 128
    float* cn = qn + 128;              // 128
    float* D  = cn + 128;              // 128*LDD

    const int tid = threadIdx.x;
    const int ty  = tid >> 3;          // 0..15 -> queries ty*8..+7
    const int tx  = tid & 7;           // 0..7  -> candidates tx*16..+15
    const int b   = blockIdx.y;
    const int q0  = blockIdx.x*128;
    const float* xb = x + (size_t)b*NN*KCH;
    const float* nb = nrm + (size_t)b*NN;

    // load Q tile (transpose to k-major): row = tid each pass
    constexpr int QI = KCH/4;
#pragma unroll
    for (int it = 0; it < QI; it++){
        int kq = it*4;
        float4 v = *(const float4*)&xb[(size_t)(q0+tid)*KCH + kq];
        Qs[(kq+0)*128+tid]=v.x; Qs[(kq+1)*128+tid]=v.y;
        Qs[(kq+2)*128+tid]=v.z; Qs[(kq+3)*128+tid]=v.w;
    }
    qn[tid] = nb[q0 + tid];

    float dist[KNN]; int idx[KNN];
#pragma unroll
    for (int i = 0; i < KNN; i++){ dist[i] = FLT_MAX; idx[i] = 0x7fffffff; }

    for (int ct = 0; ct < NN; ct += 128){
        __syncthreads();   // prior-iter D/Cs consumers done
#pragma unroll
        for (int it = 0; it < QI; it++){
            int kq = it*4;
            float4 v = *(const float4*)&xb[(size_t)(ct+tid)*KCH + kq];
            Cs[(kq+0)*128+tid]=v.x; Cs[(kq+1)*128+tid]=v.y;
            Cs[(kq+2)*128+tid]=v.z; Cs[(kq+3)*128+tid]=v.w;
        }
        cn[tid] = nb[ct + tid];
        __syncthreads();

        unsigned long long acc2[4][16];
#pragma unroll
        for (int i = 0; i < 4; i++)
#pragma unroll
            for (int j = 0; j < 16; j++) acc2[i][j] = 0ull;

#pragma unroll 2
        for (int k = 0; k < KCH; k++){
            const float* qrow = &Qs[k*128 + ty*8];
            ulonglong2 a01 = *(const ulonglong2*)qrow;
            ulonglong2 a23 = *(const ulonglong2*)(qrow + 4);
            unsigned long long ap0 = a01.x, ap1 = a01.y, ap2 = a23.x, ap3 = a23.y;
            const float* crow = &Cs[k*128 + tx*16];
#pragma unroll
            for (int g = 0; g < 4; g++){
                float4 bv = *(const float4*)(crow + g*4);
                unsigned long long b0 = dup_f(bv.x), b1 = dup_f(bv.y);
                unsigned long long b2 = dup_f(bv.z), b3 = dup_f(bv.w);
                fma2(acc2[0][g*4+0], ap0, b0); fma2(acc2[1][g*4+0], ap1, b0);
                fma2(acc2[2][g*4+0], ap2, b0); fma2(acc2[3][g*4+0], ap3, b0);
                fma2(acc2[0][g*4+1], ap0, b1); fma2(acc2[1][g*4+1], ap1, b1);
                fma2(acc2[2][g*4+1], ap2, b1); fma2(acc2[3][g*4+1], ap3, b1);
                fma2(acc2[0][g*4+2], ap0, b2); fma2(acc2[1][g*4+2], ap1, b2);
                fma2(acc2[2][g*4+2], ap2, b2); fma2(acc2[3][g*4+2], ap3, b2);
                fma2(acc2[0][g*4+3], ap0, b3); fma2(acc2[1][g*4+3], ap1, b3);
                fma2(acc2[2][g*4+3], ap2, b3); fma2(acc2[3][g*4+3], ap3, b3);
            }
        }

        // epilogue: stage distances (exact same formula/order as before)
        float qv[8], cv[16];
#pragma unroll
        for (int i = 0; i < 8; i++) qv[i] = qn[ty*8 + i];
#pragma unroll
        for (int j = 0; j < 16; j++) cv[j] = cn[tx*16 + j];
#pragma unroll
        for (int i = 0; i < 4; i++){
            float* r0 = &D[(ty*8 + 2*i    )*LDD + tx*16];
            float* r1 = &D[(ty*8 + 2*i + 1)*LDD + tx*16];
#pragma unroll
            for (int j = 0; j < 16; j++){
                float2 d = unpack2(acc2[i][j]);
                r0[j] = (qv[2*i  ] + cv[j]) - 2.f*d.x;
                r1[j] = (qv[2*i+1] + cv[j]) - 2.f*d.y;
            }
        }
        __syncthreads();

        // topk scan: 1 thread per query, 128 candidates, ascending index
        const float* drow = &D[tid*LDD];
#pragma unroll 4
        for (int i = 0; i < 128; i++)
            topk_insert(dist, idx, drow[i], ct + i);
    }

    int* ko = knnout + ((size_t)b*NN + q0 + tid)*KNN;
#pragma unroll
    for (int i = 0; i < KNN; i++) ko[i] = idx[i];
}

// ---------------- uv precompute: v = x@Wa, u = x@(Wb - Wa) ----------------
template<int CIN>
__global__ __launch_bounds__(256) void uv_kernel(
    const float* __restrict__ x, int xs, const float* __restrict__ w,
    float* __restrict__ u, float* __restrict__ v)
{
    __shared__ float sW1[CIN*64];
    __shared__ float sW2[CIN*64];
    __shared__ float sx[4][CIN];
    const int tid = threadIdx.x;
    const int p = tid >> 6, c = tid & 63;
    for (int i = tid; i < CIN*64; i += 256){
        float a = w[i];
        sW1[i] = a;
        sW2[i] = w[CIN*64 + i] - a;
    }
    const int gp = blockIdx.x*4 + p;
    for (int i = c; i < CIN; i += 64) sx[p][i] = x[(size_t)gp*xs + i];
    __syncthreads();
    float uu = 0.f, vv = 0.f;
#pragma unroll
    for (int d = 0; d < CIN; d++){
        float xv = sx[p][d];
        vv = fmaf(xv, sW1[d*64 + c], vv);
        uu = fmaf(xv, sW2[d*64 + c], uu);
    }
    u[(size_t)gp*64 + c] = uu;
    v[(size_t)gp*64 + c] = vv;
}

// ---------------- 2-layer edgeconv tail ----------------
__global__ __launch_bounds__(256) void edge2_kernel(
    const float* __restrict__ u, const float* __restrict__ v,
    const int* __restrict__ knn, const float* __restrict__ w2,
    const float* __restrict__ pa, int ia, float* __restrict__ out)
{
    __shared__ float sh1[4][64];
    const int tid = threadIdx.x;
    const int p = tid >> 6, c = tid & 63;
    float wcol[64];
#pragma unroll
    for (int d = 0; d < 64; d++) wcol[d] = __ldg(&w2[d*64 + c]);
    const float a1 = pa[ia], a2 = pa[ia+1];
    const int gp = blockIdx.x*4 + p;
    const int b  = gp >> 13;
    const float* vb = v + (size_t)b*NN*64;
    const float ur = u[(size_t)gp*64 + c];
    const int* krow = knn + (size_t)gp*KNN;
    float maxv = -FLT_MAX;
#pragma unroll
    for (int kk = 0; kk < KNN; kk++){
        int j = krow[kk];
        float h = prelu_f(ur + vb[(size_t)j*64 + c], a1);
        __syncthreads();
        sh1[p][c] = h;
        __syncthreads();
        float acc = 0.f;
#pragma unroll
        for (int d = 0; d < 64; d += 4){
            float4 hv = *(const float4*)&sh1[p][d];
            acc = fmaf(hv.x, wcol[d+0], acc);
            acc = fmaf(hv.y, wcol[d+1], acc);
            acc = fmaf(hv.z, wcol[d+2], acc);
            acc = fmaf(hv.w, wcol[d+3], acc);
        }
        maxv = fmaxf(maxv, prelu_f(acc, a2));
    }
    out[(size_t)gp*64 + c] = maxv;
}

// ---------------- 1-layer edgeconv tail ----------------
__global__ __launch_bounds__(256) void edge1_kernel(
    const float* __restrict__ u, const float* __restrict__ v,
    const int* __restrict__ knn, const float* __restrict__ pa, int ia,
    float* __restrict__ out)
{
    const int tid = threadIdx.x;
    const int p = tid >> 6, c = tid & 63;
    const float a1 = pa[ia];
    const int gp = blockIdx.x*4 + p;
    const int b  = gp >> 13;
    const float* vb = v + (size_t)b*NN*64;
    const float ur = u[(size_t)gp*64 + c];
    const int* krow = knn + (size_t)gp*KNN;
    float maxv = -FLT_MAX;
#pragma unroll
    for (int kk = 0; kk < KNN; kk++){
        int j = krow[kk];
        maxv = fmaxf(maxv, prelu_f(ur + vb[(size_t)j*64 + c], a1));
    }
    out[(size_t)gp*64 + c] = maxv;
}

// ---------------- init x5max ----------------
__global__ void init_x5max_kernel(){
    int i = blockIdx.x*256 + threadIdx.x;
    if (i < BB*1024) g_x5max[i] = 0u;
}

// ---------------- FFMA2 GEMM core: 128 rows x 64 cols per block, 128 threads ----------------
// Microtile 8x8; rows packed as natural f32x2 pairs, cols reg-dup'd.
// GATHER: A gathered from A1|A2|A3 (K=192).  COLMAX: prelu + per-batch colmax atomic.
template<bool GATHER, bool COLMAX>
__global__ __launch_bounds__(128) void gemm2_kernel(
    const float* __restrict__ A1, const float* __restrict__ A2, const float* __restrict__ A3,
    int lda, const float* __restrict__ W, int Nc, int Kd,
    const float* __restrict__ bias,
    float* __restrict__ Cout, int ldc,
    const float* __restrict__ pa, int ia)
{
    __shared__ __align__(16) float As[16][128];
    __shared__ __align__(16) float Ws[16][64];
    __shared__ float smax[16][64];

    const int tid = threadIdx.x;
    const int ty = tid >> 3;       // 0..15 -> rows ty*8..+7
    const int tx = tid & 7;        // 0..7  -> cols tx*8..+7
    const int col0 = blockIdx.x*64, row0 = blockIdx.y*128;
    const int b = row0 >> 13;
    const float slope = pa[ia];

    unsigned long long acc2[4][8];
#pragma unroll
    for (int i = 0; i < 4; i++)
#pragma unroll
        for (int j = 0; j < 8; j++) acc2[i][j] = 0ull;

    for (int k0 = 0; k0 < Kd; k0 += 16){
        const float* src; int koff, ldsrc;
        if (GATHER){
            if (k0 < 64)      { src = A1; koff = k0;       }
            else if (k0 < 128){ src = A2; koff = k0 - 64;  }
            else              { src = A3; koff = k0 - 128; }
            ldsrc = 64;
        } else { src = A1; koff = k0; ldsrc = lda; }

        float4 av[4]; float4 wv[2];
#pragma unroll
        for (int it = 0; it < 4; it++)
            av[it] = *(const float4*)&src[(size_t)(row0 + tid)*ldsrc + koff + it*4];
#pragma unroll
        for (int it = 0; it < 2; it++){
            int f = tid + it*128;
            wv[it] = *(const float4*)&W[(size_t)(k0 + (f >> 4))*Nc + col0 + (f & 15)*4];
        }
        __syncthreads();
#pragma unroll
        for (int it = 0; it < 4; it++){
            int kq = it*4;
            As[kq+0][tid]=av[it].x; As[kq+1][tid]=av[it].y;
            As[kq+2][tid]=av[it].z; As[kq+3][tid]=av[it].w;
        }
#pragma unroll
        for (int it = 0; it < 2; it++){
            int f = tid + it*128;
            *(float4*)&Ws[f >> 4][(f & 15)*4] = wv[it];
        }
        __syncthreads();

#pragma unroll 4
        for (int kk = 0; kk < 16; kk++){
            const float* arow = &As[kk][ty*8];
            ulonglong2 a01 = *(const ulonglong2*)arow;
            ulonglong2 a23 = *(const ulonglong2*)(arow + 4);
            unsigned long long ap0 = a01.x, ap1 = a01.y, ap2 = a23.x, ap3 = a23.y;
            const float* wrow = &Ws[kk][tx*8];
            float4 w0 = *(const float4*)wrow;
            float4 w1 = *(const float4*)(wrow + 4);
            unsigned long long bd[8] = {
                dup_f(w0.x), dup_f(w0.y), dup_f(w0.z), dup_f(w0.w),
                dup_f(w1.x), dup_f(w1.y), dup_f(w1.z), dup_f(w1.w)};
#pragma unroll
            for (int j = 0; j < 8; j++){
                fma2(acc2[0][j], ap0, bd[j]);
                fma2(acc2[1][j], ap1, bd[j]);
                fma2(acc2[2][j], ap2, bd[j]);
                fma2(acc2[3][j], ap3, bd[j]);
            }
        }
        __syncthreads();
    }

    if (!COLMAX){
        float bj[8];
#pragma unroll
        for (int j = 0; j < 8; j++) bj[j] = bias ? bias[b*Nc + col0 + tx*8 + j] : 0.f;
#pragma unroll
        for (int i = 0; i < 4; i++){
            float r0[8], r1[8];
#pragma unroll
            for (int j = 0; j < 8; j++){
                float2 d = unpack2(acc2[i][j]);
                r0[j] = prelu_f(d.x + bj[j], slope);
                r1[j] = prelu_f(d.y + bj[j], slope);
            }
            float* o0 = &Cout[(size_t)(row0 + ty*8 + 2*i    )*ldc + col0 + tx*8];
            float* o1 = &Cout[(size_t)(row0 + ty*8 + 2*i + 1)*ldc + col0 + tx*8];
            *(float4*)&o0[0] = make_float4(r0[0],r0[1],r0[2],r0[3]);
            *(float4*)&o0[4] = make_float4(r0[4],r0[5],r0[6],r0[7]);
            *(float4*)&o1[0] = make_float4(r1[0],r1[1],r1[2],r1[3]);
            *(float4*)&o1[4] = make_float4(r1[4],r1[5],r1[6],r1[7]);
        }
    } else {
#pragma unroll
        for (int j = 0; j < 8; j++){
            float m = -FLT_MAX;
#pragma unroll
            for (int i = 0; i < 4; i++){
                float2 d = unpack2(acc2[i][j]);
                m = fmaxf(m, prelu_f(d.x, slope));
                m = fmaxf(m, prelu_f(d.y, slope));
            }
            smax[ty][tx*8 + j] = m;
        }
        __syncthreads();
        if (tid < 8){
#pragma unroll
            for (int j = 0; j < 8; j++){
                float mm = smax[0][tid*8 + j];
#pragma unroll
                for (int t = 1; t < 16; t++) mm = fmaxf(mm, smax[t][tid*8 + j]);
                atomicMax(&g_x5max[b*1024 + col0 + tid*8 + j], enc_f(mm));
            }
        }
    }
}

// ---------------- bias7 ----------------
__global__ __launch_bounds__(256) void bias7_kernel(const float* __restrict__ w7){
    int b = blockIdx.x, c = threadIdx.x;
    float acc = 0.f;
    for (int d = 0; d < 1024; d++){
        float v = dec_f(g_x5max[b*1024 + d]);
        acc = fmaf(v, w7[(size_t)(192 + d)*256 + c], acc);
    }
    g_bias7[b*256 + c] = acc;
}

// ---------------- final layer ----------------
__global__ __launch_bounds__(256) void head_out_kernel(
    const float* __restrict__ yc, const float* __restrict__ w10,
    const float* __restrict__ pa, float* __restrict__ out)
{
    __shared__ float sw[256];
    if (threadIdx.x < 256) sw[threadIdx.x] = w10[threadIdx.x];
    __syncthreads();
    const float slope = pa[9];
    const int row = blockIdx.x*256 + threadIdx.x;
    const float* yr = yc + (size_t)row*128;
    float a0 = 0.f, a1 = 0.f;
#pragma unroll
    for (int d = 0; d < 128; d++){
        float v = yr[d];
        a0 = fmaf(v, sw[2*d + 0], a0);
        a1 = fmaf(v, sw[2*d + 1], a1);
    }
    out[row*2 + 0] = prelu_f(a0, slope);
    out[row*2 + 1] = prelu_f(a1, slope);
}

// ---------------- host orchestration ----------------
extern "C" void kernel_launch(void* const* d_in, const int* in_sizes, int n_in,
                              void* d_out, int out_size)
{
    (void)in_sizes; (void)n_in; (void)out_size;
    const float* targets = (const float*)d_in[0];
    const float* w[10];
    for (int i = 0; i < 10; i++) w[i] = (const float*)d_in[1 + i];
    const float* pa = (const float*)d_in[11];
    float* out = (float*)d_out;

    void *px0, *px1, *px2, *px3, *pu, *pv, *pn, *pknn, *pya, *pyb, *pb7;
    cudaGetSymbolAddress(&px0, g_x0p);
    cudaGetSymbolAddress(&px1, g_x1);
    cudaGetSymbolAddress(&px2, g_x2);
    cudaGetSymbolAddress(&px3, g_x3);
    cudaGetSymbolAddress(&pu,  g_u);
    cudaGetSymbolAddress(&pv,  g_v);
    cudaGetSymbolAddress(&pn,  g_nrm);
    cudaGetSymbolAddress(&pknn, g_knn);
    cudaGetSymbolAddress(&pya, g_ya);
    cudaGetSymbolAddress(&pyb, g_yb);
    cudaGetSymbolAddress(&pb7, g_bias7);

    float* x0 = (float*)px0; float* x1 = (float*)px1;
    float* x2 = (float*)px2; float* x3 = (float*)px3;
    float* uu = (float*)pu;  float* vv = (float*)pv;
    float* nr = (float*)pn;
    int*   kn = (int*)pknn;
    float* ya = (float*)pya; float* yb = (float*)pyb;
    float* b7 = (float*)pb7;

    // opt-in to large dynamic smem for kNN kernels (idempotent)
    const int SM8  = (8*128*2 + 256)*4 + 128*LDD*4;
    const int SM64 = (64*128*2 + 256)*4 + 128*LDD*4;
    cudaFuncSetAttribute(knn_tile_kernel<8>,  cudaFuncAttributeMaxDynamicSharedMemorySize, SM8);
    cudaFuncSetAttribute(knn_tile_kernel<64>, cudaFuncAttributeMaxDynamicSharedMemorySize, SM64);

    dim3 kgrid(NN/128, BB);

    // stage 0: x0p = [t,t,0,0]
    build_x0p_kernel<<<MTOT/256, 256>>>(targets);

    // stage 1 (CIN=6 via padded 8)
    norms_kernel<8><<<MTOT/256, 256>>>(x0, nr);
    knn_tile_kernel<8><<<kgrid, 128, SM8>>>(x0, nr, kn);
    uv_kernel<6><<<MTOT/4, 256>>>(x0, 8, w[0], uu, vv);
    edge2_kernel<<<MTOT/4, 256>>>(uu, vv, kn, w[1], pa, 0, x1);

    // stage 2
    norms_kernel<64><<<MTOT/256, 256>>>(x1, nr);
    knn_tile_kernel<64><<<kgrid, 128, SM64>>>(x1, nr, kn);
    uv_kernel<64><<<MTOT/4, 256>>>(x1, 64, w[2], uu, vv);
    edge2_kernel<<<MTOT/4, 256>>>(uu, vv, kn, w[3], pa, 2, x2);

    // stage 3 (single layer)
    norms_kernel<64><<<MTOT/256, 256>>>(x2, nr);
    knn_tile_kernel<64><<<kgrid, 128, SM64>>>(x2, nr, kn);
    uv_kernel<64><<<MTOT/4, 256>>>(x2, 64, w[4], uu, vv);
    edge1_kernel<<<MTOT/4, 256>>>(uu, vv, kn, pa, 4, x3);

    // head
    init_x5max_kernel<<<(BB*1024 + 255)/256, 256>>>();
    // w6: colmax over prelu([x1,x2,x3] @ w6), K=192, N=1024
    gemm2_kernel<true, true><<<dim3(1024/64, MTOT/128), 128>>>(
        x1, x2, x3, 64, w[5], 1024, 192, nullptr, nullptr, 0, pa, 5);
    bias7_kernel<<<BB, 256>>>(w[6]);
    // w7: ya = prelu([x1,x2,x3] @ w7[:192] + bias7), N=256
    gemm2_kernel<true, false><<<dim3(256/64, MTOT/128), 128>>>(
        x1, x2, x3, 64, w[6], 256, 192, b7, ya, 256, pa, 6);
    // w8: yb = prelu(ya @ w8), K=256, N=256
    gemm2_kernel<false, false><<<dim3(256/64, MTOT/128), 128>>>(
        ya, nullptr, nullptr, 256, w[7], 256, 256, nullptr, yb, 256, pa, 7);
    // w9: ya[:, :128] = prelu(yb @ w9), K=256, N=128
    gemm2_kernel<false, false><<<dim3(128/64, MTOT/128), 128>>>(
        yb, nullptr, nullptr, 256, w[8], 128, 256, nullptr, ya, 128, pa, 8);
    head_out_kernel<<<MTOT/256, 256>>>(ya, w[9], pa, out);
}

// round 8
// speedup vs baseline: 1.6395x; 1.6395x over previous
#include <cuda_runtime.h>
#include <cuda_bf16.h>
#include <cfloat>
#include <cstdint>
#include <math.h>

#define BB 4
#define NN 8192
#define KNN 10
#define MTOT (BB*NN)
#define LDD 129    // padded row stride of distance tile (scalar knn)
#define LDD2 130   // padded row stride of distance tile (hmma knn; even for float2 stores)
#define PADK 72    // bf16 per smem row (64 data + 8 pad) -> conflict-free ldmatrix

// ---------------- scratch (device globals; no allocation allowed) ----------------
__device__ float         g_x0p[MTOT*8];
__device__ float         g_x1[MTOT*64];
__device__ float         g_x2[MTOT*64];
__device__ float         g_x3[MTOT*64];
__device__ float         g_u[MTOT*64];
__device__ float         g_v[MTOT*64];
__device__ float         g_nrm[MTOT];
__device__ int           g_knn[MTOT*KNN];
__device__ unsigned      g_x5max[BB*1024];
__device__ float         g_bias7[BB*256];
__device__ float         g_ya[MTOT*256];
__device__ float         g_yb[MTOT*256];
__device__ __nv_bfloat16 g_bh[MTOT*64];
__device__ __nv_bfloat16 g_bl[MTOT*64];

// ---------------- helpers ----------------
__device__ __forceinline__ float prelu_f(float v, float a){ return v >= 0.f ? v : a*v; }

__device__ __forceinline__ unsigned enc_f(float f){
    unsigned u = __float_as_uint(f);
    return (u & 0x80000000u) ? ~u : (u | 0x80000000u);
}
__device__ __forceinline__ float dec_f(unsigned u){
    return (u & 0x80000000u) ? __uint_as_float(u & 0x7fffffffu) : __uint_as_float(~u);
}

__device__ __forceinline__ void topk_insert(float (&dist)[KNN], int (&idx)[KNN], float d, int j){
    if (d < dist[KNN-1]){
        float cd = d; int cj = j;
#pragma unroll
        for (int p = 0; p < KNN; p++){
            if (cd < dist[p]){
                float td = dist[p]; int tj = idx[p];
                dist[p] = cd; idx[p] = cj;
                cd = td; cj = tj;
            }
        }
    }
}

__device__ __forceinline__ uint32_t smem_u32(const void* p){
    uint32_t a;
    asm("{ .reg .u64 t; cvta.to.shared.u64 t, %1; cvt.u32.u64 %0, t; }" : "=r"(a) : "l"(p));
    return a;
}
__device__ __forceinline__ void ldsm_x4(uint32_t& r0, uint32_t& r1, uint32_t& r2, uint32_t& r3, uint32_t addr){
    asm volatile("ldmatrix.sync.aligned.m8n8.x4.shared.b16 {%0,%1,%2,%3}, [%4];"
                 : "=r"(r0), "=r"(r1), "=r"(r2), "=r"(r3) : "r"(addr));
}
__device__ __forceinline__ void mma16816(float& c0, float& c1, float& c2, float& c3,
                                         uint32_t a0, uint32_t a1, uint32_t a2, uint32_t a3,
                                         uint32_t b0, uint32_t b1){
    asm volatile(
        "mma.sync.aligned.m16n8k16.row.col.f32.bf16.bf16.f32 "
        "{%0,%1,%2,%3}, {%4,%5,%6,%7}, {%8,%9}, {%0,%1,%2,%3};"
        : "+f"(c0), "+f"(c1), "+f"(c2), "+f"(c3)
        : "r"(a0), "r"(a1), "r"(a2), "r"(a3), "r"(b0), "r"(b1));
}

// ---------------- build x0p = [t,t,0,0] padded to 8 ----------------
__global__ __launch_bounds__(256) void build_x0p_kernel(const float* __restrict__ t){
    int i = blockIdx.x*256 + threadIdx.x;
    float t0 = t[i*3+0], t1 = t[i*3+1], t2 = t[i*3+2];
    float4* o = (float4*)(g_x0p + (size_t)i*8);
    o[0] = make_float4(t0, t1, t2, t0);
    o[1] = make_float4(t1, t2, 0.f, 0.f);
}

// ---------------- row squared norms ----------------
template<int KCH>
__global__ __launch_bounds__(256) void norms_kernel(const float* __restrict__ x, float* __restrict__ nrm){
    int r = blockIdx.x*256 + threadIdx.x;
    const float* xr = x + (size_t)r*KCH;
    float s = 0.f;
#pragma unroll
    for (int k = 0; k < KCH; k++) s = fmaf(xr[k], xr[k], s);
    nrm[r] = s;
}

// ---------------- bf16 hi/lo split ----------------
__global__ __launch_bounds__(256) void split_kernel(const float* __restrict__ x){
    int i = blockIdx.x*256 + threadIdx.x;
    float f = x[i];
    __nv_bfloat16 h = __float2bfloat16(f);
    float r = f - __bfloat162float(h);
    g_bh[i] = h;
    g_bl[i] = __float2bfloat16(r);
}

// ---------------- scalar kNN (stage 1, C=8 padded) — R3 version ----------------
template<int KCH>
__global__ __launch_bounds__(256, 1) void knn_tile_kernel(
    const float* __restrict__ x, const float* __restrict__ nrm, int* __restrict__ knnout)
{
    extern __shared__ float sm[];
    float* Qs = sm;
    float* Cs = Qs + KCH*128;
    float* qn = Cs + KCH*128;
    float* cn = qn + 128;
    float* D  = cn + 128;

    const int tid = threadIdx.x;
    const int b   = blockIdx.y;
    const int q0  = blockIdx.x*128;
    const float* xb = x + (size_t)b*NN*KCH;
    const float* nb = nrm + (size_t)b*NN;

    constexpr int NV = 128*(KCH/4);
    for (int f = tid; f < NV; f += 256){
        int row = f & 127;
        int kq  = (f >> 7) * 4;
        float4 v = *(const float4*)&xb[(size_t)(q0+row)*KCH + kq];
        Qs[(kq+0)*128+row]=v.x; Qs[(kq+1)*128+row]=v.y;
        Qs[(kq+2)*128+row]=v.z; Qs[(kq+3)*128+row]=v.w;
    }
    if (tid < 128) qn[tid] = nb[q0 + tid];

    float dist[KNN]; int idx[KNN];
#pragma unroll
    for (int i = 0; i < KNN; i++){ dist[i] = FLT_MAX; idx[i] = 0x7fffffff; }

    const int ty = tid >> 4;
    const int tx = tid & 15;
    int rr[8], cc[8];
#pragma unroll
    for (int i = 0; i < 4; i++){ rr[i] = ty*4 + i; rr[i+4] = 64 + ty*4 + i; }
#pragma unroll
    for (int j = 0; j < 4; j++){ cc[j] = tx*4 + j; cc[j+4] = 64 + tx*4 + j; }
    const int qh = tid & 127;
    const int hh = tid >> 7;

    for (int ct = 0; ct < NN; ct += 128){
        __syncthreads();
        for (int f = tid; f < NV; f += 256){
            int row = f & 127;
            int kq  = (f >> 7) * 4;
            float4 v = *(const float4*)&xb[(size_t)(ct+row)*KCH + kq];
            Cs[(kq+0)*128+row]=v.x; Cs[(kq+1)*128+row]=v.y;
            Cs[(kq+2)*128+row]=v.z; Cs[(kq+3)*128+row]=v.w;
        }
        if (tid < 128) cn[tid] = nb[ct + tid];
        __syncthreads();

        float acc[8][8];
#pragma unroll
        for (int i = 0; i < 8; i++)
#pragma unroll
            for (int j = 0; j < 8; j++) acc[i][j] = 0.f;

#pragma unroll 8
        for (int k = 0; k < KCH; k++){
            float a[8], bb[8];
            *(float4*)&a[0]  = *(const float4*)&Qs[k*128 + ty*4];
            *(float4*)&a[4]  = *(const float4*)&Qs[k*128 + 64 + ty*4];
            *(float4*)&bb[0] = *(const float4*)&Cs[k*128 + tx*4];
            *(float4*)&bb[4] = *(const float4*)&Cs[k*128 + 64 + tx*4];
#pragma unroll
            for (int i = 0; i < 8; i++)
#pragma unroll
                for (int j = 0; j < 8; j++) acc[i][j] = fmaf(a[i], bb[j], acc[i][j]);
        }

        float qv[8], cv[8];
#pragma unroll
        for (int i = 0; i < 8; i++) qv[i] = qn[rr[i]];
#pragma unroll
        for (int j = 0; j < 8; j++) cv[j] = cn[cc[j]];
#pragma unroll
        for (int i = 0; i < 8; i++)
#pragma unroll
            for (int j = 0; j < 8; j++)
                D[rr[i]*LDD + cc[j]] = (qv[i] + cv[j]) - 2.f*acc[i][j];
        __syncthreads();

        const float* drow = &D[qh*LDD + hh*64];
        const int cbase = ct + hh*64;
#pragma unroll 4
        for (int i = 0; i < 64; i++)
            topk_insert(dist, idx, drow[i], cbase + i);
    }

    __syncthreads();
    float* Ld = D;
    int*   Li = (int*)(D + 4096);
#pragma unroll
    for (int i = 0; i < KNN; i++){ Ld[tid*KNN + i] = dist[i]; Li[tid*KNN + i] = idx[i]; }
    __syncthreads();
    if (tid < 128){
        const float* da = &Ld[tid*KNN];        const int* ja = &Li[tid*KNN];
        const float* db = &Ld[(tid+128)*KNN];  const int* jb = &Li[(tid+128)*KNN];
        int* ko = knnout + ((size_t)b*NN + q0 + tid)*KNN;
        int ia = 0, ib = 0;
#pragma unroll
        for (int i = 0; i < KNN; i++){
            float d0 = da[ia], d1 = db[ib];
            int   j0 = ja[ia], j1 = jb[ib];
            bool A = (d0 < d1) || (d0 == d1 && j0 < j1);
            ko[i] = A ? j0 : j1;
            if (A) ia++; else ib++;
        }
    }
}

// ---------------- kNN via warp HMMA bf16-split (C=64 stages) ----------------
// 256 threads / 8 warps; block = 128 queries. Warp w owns rows w*16..+15, all 128 cols.
// 3-term split: dot = Ah*Bh + Ah*Bl + Al*Bh, fp32 accum in mma.
// smem byte offsets (dynamic, base 16B-aligned):
#define HS_AH 0
#define HS_AL 18432
#define HS_BH 36864
#define HS_BL 55296
#define HS_QN 73728
#define HS_CN 74240
#define HS_D  74752
#define HS_TOTAL (74752 + 128*LDD2*4)   // 141312

__global__ __launch_bounds__(256, 1) void knn_hmma_kernel(
    const __nv_bfloat16* __restrict__ xh, const __nv_bfloat16* __restrict__ xl,
    const float* __restrict__ nrm, int* __restrict__ knnout)
{
    extern __shared__ char smp[];
    const uint32_t sbase = smem_u32(smp);

    const int tid = threadIdx.x;
    const int w   = tid >> 5;
    const int l   = tid & 31;
    const int b   = blockIdx.y;
    const int q0  = blockIdx.x*128;
    const size_t rowbase = (size_t)b*NN;
    const __nv_bfloat16* xhb = xh + rowbase*64;
    const __nv_bfloat16* xlb = xl + rowbase*64;
    const float* nb = nrm + rowbase;

    float* qn = (float*)(smp + HS_QN);
    float* cn = (float*)(smp + HS_CN);
    float* D  = (float*)(smp + HS_D);

    // ldmatrix lane geometry (quadrant mapping for x4)
    const int lq  = l >> 3;
    const int lr  = l & 7;
    const int rowq = ((lq & 1) << 3) + lr;   // 0..15 within 16-row tile
    const int colq = (lq >> 1) << 3;         // 0 or 8 (bf16 col within k16 chunk)

    // A tiles (queries, resident): rows 0..127, 64 bf16 -> 8 uint4 per row
    for (int f = tid; f < 128*8; f += 256){
        int row = f >> 3, seg = f & 7;
        uint32_t dst = row*PADK*2 + seg*16;
        *(uint4*)(smp + HS_AH + dst) = *(const uint4*)&xhb[(size_t)(q0+row)*64 + seg*8];
        *(uint4*)(smp + HS_AL + dst) = *(const uint4*)&xlb[(size_t)(q0+row)*64 + seg*8];
    }
    if (tid < 128) qn[tid] = nb[q0 + tid];

    float dist[KNN]; int idx[KNN];
#pragma unroll
    for (int i = 0; i < KNN; i++){ dist[i] = FLT_MAX; idx[i] = 0x7fffffff; }

    // per-lane base addresses
    const uint32_t aArow = sbase + (uint32_t)((w*16 + rowq)*PADK + colq)*2;
    const int qh = tid & 127;   // topk query
    const int hh = tid >> 7;    // topk half

    for (int ct = 0; ct < NN; ct += 128){
        __syncthreads();
        // B tiles (candidates)
        for (int f = tid; f < 128*8; f += 256){
            int row = f >> 3, seg = f & 7;
            uint32_t dst = row*PADK*2 + seg*16;
            *(uint4*)(smp + HS_BH + dst) = *(const uint4*)&xhb[(size_t)(ct+row)*64 + seg*8];
            *(uint4*)(smp + HS_BL + dst) = *(const uint4*)&xlb[(size_t)(ct+row)*64 + seg*8];
        }
        if (tid < 128) cn[tid] = nb[ct + tid];
        __syncthreads();

        float acc[16][4];
#pragma unroll
        for (int t = 0; t < 16; t++)
#pragma unroll
            for (int j = 0; j < 4; j++) acc[t][j] = 0.f;

#pragma unroll
        for (int kc = 0; kc < 4; kc++){
            uint32_t ah0, ah1, ah2, ah3, al0, al1, al2, al3;
            ldsm_x4(ah0, ah1, ah2, ah3, aArow + HS_AH + kc*32);
            ldsm_x4(al0, al1, al2, al3, aArow + HS_AL + kc*32);
#pragma unroll
            for (int p = 0; p < 8; p++){
                uint32_t bb = sbase + (uint32_t)((p*16 + rowq)*PADK + colq)*2 + kc*32;
                uint32_t bh0, bh1, bh2, bh3, bl0, bl1, bl2, bl3;
                ldsm_x4(bh0, bh1, bh2, bh3, bb + HS_BH);
                ldsm_x4(bl0, bl1, bl2, bl3, bb + HS_BL);
                float* c0 = acc[2*p];
                float* c1 = acc[2*p+1];
                mma16816(c0[0], c0[1], c0[2], c0[3], ah0, ah1, ah2, ah3, bh0, bh2);
                mma16816(c1[0], c1[1], c1[2], c1[3], ah0, ah1, ah2, ah3, bh1, bh3);
                mma16816(c0[0], c0[1], c0[2], c0[3], ah0, ah1, ah2, ah3, bl0, bl2);
                mma16816(c1[0], c1[1], c1[2], c1[3], ah0, ah1, ah2, ah3, bl1, bl3);
                mma16816(c0[0], c0[1], c0[2], c0[3], al0, al1, al2, al3, bh0, bh2);
                mma16816(c1[0], c1[1], c1[2], c1[3], al0, al1, al2, al3, bh1, bh3);
            }
        }

        // epilogue: distances into D
        {
            const int r0 = w*16 + (l >> 2);
            const float qn0 = qn[r0], qn1 = qn[r0 + 8];
#pragma unroll
            for (int t = 0; t < 16; t++){
                int c = t*8 + (l & 3)*2;
                float c0 = cn[c], c1 = cn[c+1];
                *(float2*)&D[r0*LDD2 + c]     = make_float2((qn0 + c0) - 2.f*acc[t][0],
                                                            (qn0 + c1) - 2.f*acc[t][1]);
                *(float2*)&D[(r0+8)*LDD2 + c] = make_float2((qn1 + c0) - 2.f*acc[t][2],
                                                            (qn1 + c1) - 2.f*acc[t][3]);
            }
        }
        __syncthreads();

        // topk scan: 2 threads per query, 64 candidates each (same as R3)
        const float* drow = &D[qh*LDD2 + hh*64];
        const int cbase = ct + hh*64;
#pragma unroll 4
        for (int i = 0; i < 64; i++)
            topk_insert(dist, idx, drow[i], cbase + i);
    }

    // merge the two half-lists per query (stable, exact)
    __syncthreads();
    float* Ld = D;
    int*   Li = (int*)(D + 4096);
#pragma unroll
    for (int i = 0; i < KNN; i++){ Ld[tid*KNN + i] = dist[i]; Li[tid*KNN + i] = idx[i]; }
    __syncthreads();
    if (tid < 128){
        const float* da = &Ld[tid*KNN];        const int* ja = &Li[tid*KNN];
        const float* db = &Ld[(tid+128)*KNN];  const int* jb = &Li[(tid+128)*KNN];
        int* ko = knnout + (rowbase + q0 + tid)*KNN;
        int ia = 0, ib = 0;
#pragma unroll
        for (int i = 0; i < KNN; i++){
            float d0 = da[ia], d1 = db[ib];
            int   j0 = ja[ia], j1 = jb[ib];
            bool A = (d0 < d1) || (d0 == d1 && j0 < j1);
            ko[i] = A ? j0 : j1;
            if (A) ia++; else ib++;
        }
    }
}

// ---------------- uv precompute: v = x@Wa, u = x@(Wb - Wa) ----------------
template<int CIN>
__global__ __launch_bounds__(256) void uv_kernel(
    const float* __restrict__ x, int xs, const float* __restrict__ w,
    float* __restrict__ u, float* __restrict__ v)
{
    __shared__ float sW1[CIN*64];
    __shared__ float sW2[CIN*64];
    __shared__ float sx[4][CIN];
    const int tid = threadIdx.x;
    const int p = tid >> 6, c = tid & 63;
    for (int i = tid; i < CIN*64; i += 256){
        float a = w[i];
        sW1[i] = a;
        sW2[i] = w[CIN*64 + i] - a;
    }
    const int gp = blockIdx.x*4 + p;
    for (int i = c; i < CIN; i += 64) sx[p][i] = x[(size_t)gp*xs + i];
    __syncthreads();
    float uu = 0.f, vv = 0.f;
#pragma unroll
    for (int d = 0; d < CIN; d++){
        float xv = sx[p][d];
        vv = fmaf(xv, sW1[d*64 + c], vv);
        uu = fmaf(xv, sW2[d*64 + c], uu);
    }
    u[(size_t)gp*64 + c] = uu;
    v[(size_t)gp*64 + c] = vv;
}

// ---------------- 2-layer edgeconv tail ----------------
__global__ __launch_bounds__(256) void edge2_kernel(
    const float* __restrict__ u, const float* __restrict__ v,
    const int* __restrict__ knn, const float* __restrict__ w2,
    const float* __restrict__ pa, int ia, float* __restrict__ out)
{
    __shared__ float sh1[4][64];
    const int tid = threadIdx.x;
    const int p = tid >> 6, c = tid & 63;
    float wcol[64];
#pragma unroll
    for (int d = 0; d < 64; d++) wcol[d] = __ldg(&w2[d*64 + c]);
    const float a1 = pa[ia], a2 = pa[ia+1];
    const int gp = blockIdx.x*4 + p;
    const int b  = gp >> 13;
    const float* vb = v + (size_t)b*NN*64;
    const float ur = u[(size_t)gp*64 + c];
    const int* krow = knn + (size_t)gp*KNN;
    float maxv = -FLT_MAX;
#pragma unroll
    for (int kk = 0; kk < KNN; kk++){
        int j = krow[kk];
        float h = prelu_f(ur + vb[(size_t)j*64 + c], a1);
        __syncthreads();
        sh1[p][c] = h;
        __syncthreads();
        float acc = 0.f;
#pragma unroll
        for (int d = 0; d < 64; d += 4){
            float4 hv = *(const float4*)&sh1[p][d];
            acc = fmaf(hv.x, wcol[d+0], acc);
            acc = fmaf(hv.y, wcol[d+1], acc);
            acc = fmaf(hv.z, wcol[d+2], acc);
            acc = fmaf(hv.w, wcol[d+3], acc);
        }
        maxv = fmaxf(maxv, prelu_f(acc, a2));
    }
    out[(size_t)gp*64 + c] = maxv;
}

// ---------------- 1-layer edgeconv tail ----------------
__global__ __launch_bounds__(256) void edge1_kernel(
    const float* __restrict__ u, const float* __restrict__ v,
    const int* __restrict__ knn, const float* __restrict__ pa, int ia,
    float* __restrict__ out)
{
    const int tid = threadIdx.x;
    const int p = tid >> 6, c = tid & 63;
    const float a1 = pa[ia];
    const int gp = blockIdx.x*4 + p;
    const int b  = gp >> 13;
    const float* vb = v + (size_t)b*NN*64;
    const float ur = u[(size_t)gp*64 + c];
    const int* krow = knn + (size_t)gp*KNN;
    float maxv = -FLT_MAX;
#pragma unroll
    for (int kk = 0; kk < KNN; kk++){
        int j = krow[kk];
        maxv = fmaxf(maxv, prelu_f(ur + vb[(size_t)j*64 + c], a1));
    }
    out[(size_t)gp*64 + c] = maxv;
}

// ---------------- init x5max ----------------
__global__ void init_x5max_kernel(){
    int i = blockIdx.x*256 + threadIdx.x;
    if (i < BB*1024) g_x5max[i] = 0u;
}

// ---------------- GEMM over K=192 with A gathered from x1|x2|x3 ----------------
template<bool COLMAX>
__global__ __launch_bounds__(256) void gemm192_kernel(
    const float* __restrict__ A1, const float* __restrict__ A2, const float* __restrict__ A3,
    const float* __restrict__ W, int Nc,
    const float* __restrict__ bias,
    float* __restrict__ Cout, int ldc,
    const float* __restrict__ pa, int ia)
{
    __shared__ __align__(16) float As[16][64];
    __shared__ __align__(16) float Ws[16][64];
    __shared__ float smax[16][64];

    const int tid = threadIdx.x;
    const int tx = tid & 15, ty = tid >> 4;
    const int col0 = blockIdx.x*64, row0 = blockIdx.y*64;
    const int b = row0 >> 13;
    const float slope = pa[ia];

    float acc[4][4];
#pragma unroll
    for (int i = 0; i < 4; i++)
#pragma unroll
        for (int j = 0; j < 4; j++) acc[i][j] = 0.f;

    const int lr  = tid >> 2;
    const int lk4 = (tid & 3)*4;

    for (int k0 = 0; k0 < 192; k0 += 16){
        const float* src; int koff;
        if (k0 < 64)      { src = A1; koff = k0;       }
        else if (k0 < 128){ src = A2; koff = k0 - 64;  }
        else              { src = A3; koff = k0 - 128; }
        float4 av = *(const float4*)&src[(size_t)(row0 + lr)*64 + koff + lk4];
        float4 wv = *(const float4*)&W[(size_t)(k0 + (tid >> 4))*Nc + col0 + (tid & 15)*4];
        __syncthreads();
        As[lk4+0][lr] = av.x; As[lk4+1][lr] = av.y; As[lk4+2][lr] = av.z; As[lk4+3][lr] = av.w;
        *(float4*)&Ws[tid >> 4][(tid & 15)*4] = wv;
        __syncthreads();
#pragma unroll
        for (int kk = 0; kk < 16; kk++){
            float a[4], w[4];
            *(float4*)a = *(const float4*)&As[kk][ty*4];
            *(float4*)w = *(const float4*)&Ws[kk][tx*4];
#pragma unroll
            for (int i = 0; i < 4; i++)
#pragma unroll
                for (int j = 0; j < 4; j++) acc[i][j] = fmaf(a[i], w[j], acc[i][j]);
        }
    }

    if (!COLMAX){
        float bj[4];
#pragma unroll
        for (int j = 0; j < 4; j++) bj[j] = bias ? bias[b*Nc + col0 + tx*4 + j] : 0.f;
#pragma unroll
        for (int i = 0; i < 4; i++){
#pragma unroll
            for (int j = 0; j < 4; j++){
                float v = acc[i][j] + bj[j];
                v = prelu_f(v, slope);
                Cout[(size_t)(row0 + ty*4 + i)*ldc + col0 + tx*4 + j] = v;
            }
        }
    } else {
#pragma unroll
        for (int j = 0; j < 4; j++){
            float m = -FLT_MAX;
#pragma unroll
            for (int i = 0; i < 4; i++) m = fmaxf(m, prelu_f(acc[i][j], slope));
            smax[ty][tx*4 + j] = m;
        }
        __syncthreads();
        if (ty == 0){
#pragma unroll
            for (int j = 0; j < 4; j++){
                float mm = smax[0][tx*4 + j];
#pragma unroll
                for (int t = 1; t < 16; t++) mm = fmaxf(mm, smax[t][tx*4 + j]);
                atomicMax(&g_x5max[b*1024 + col0 + tx*4 + j], enc_f(mm));
            }
        }
    }
}

// ---------------- bias7 ----------------
__global__ __launch_bounds__(256) void bias7_kernel(const float* __restrict__ w7){
    int b = blockIdx.x, c = threadIdx.x;
    float acc = 0.f;
    for (int d = 0; d < 1024; d++){
        float v = dec_f(g_x5max[b*1024 + d]);
        acc = fmaf(v, w7[(size_t)(192 + d)*256 + c], acc);
    }
    g_bias7[b*256 + c] = acc;
}

// ---------------- generic fp32 GEMM + prelu ----------------
__global__ __launch_bounds__(256) void gemm_kernel(
    const float* __restrict__ A, int lda,
    const float* __restrict__ W, int Nc, int Kd,
    float* __restrict__ Cout, int ldc,
    const float* __restrict__ pa, int ia)
{
    __shared__ __align__(16) float As[16][64];
    __shared__ __align__(16) float Ws[16][64];

    const int tid = threadIdx.x;
    const int tx = tid & 15, ty = tid >> 4;
    const int col0 = blockIdx.x*64, row0 = blockIdx.y*64;
    const float slope = pa[ia];

    float acc[4][4];
#pragma unroll
    for (int i = 0; i < 4; i++)
#pragma unroll
        for (int j = 0; j < 4; j++) acc[i][j] = 0.f;

    const int lr  = tid >> 2;
    const int lk4 = (tid & 3)*4;

    for (int k0 = 0; k0 < Kd; k0 += 16){
        float4 av = *(const float4*)&A[(size_t)(row0 + lr)*lda + k0 + lk4];
        float4 wv = *(const float4*)&W[(size_t)(k0 + (tid >> 4))*Nc + col0 + (tid & 15)*4];
        __syncthreads();
        As[lk4+0][lr] = av.x; As[lk4+1][lr] = av.y; As[lk4+2][lr] = av.z; As[lk4+3][lr] = av.w;
        *(float4*)&Ws[tid >> 4][(tid & 15)*4] = wv;
        __syncthreads();
#pragma unroll
        for (int kk = 0; kk < 16; kk++){
            float a[4], w[4];
            *(float4*)a = *(const float4*)&As[kk][ty*4];
            *(float4*)w = *(const float4*)&Ws[kk][tx*4];
#pragma unroll
            for (int i = 0; i < 4; i++)
#pragma unroll
                for (int j = 0; j < 4; j++) acc[i][j] = fmaf(a[i], w[j], acc[i][j]);
        }
    }
#pragma unroll
    for (int i = 0; i < 4; i++)
#pragma unroll
        for (int j = 0; j < 4; j++){
            float v = prelu_f(acc[i][j], slope);
            Cout[(size_t)(row0 + ty*4 + i)*ldc + col0 + tx*4 + j] = v;
        }
}

// ---------------- final layer ----------------
__global__ __launch_bounds__(256) void head_out_kernel(
    const float* __restrict__ yc, const float* __restrict__ w10,
    const float* __restrict__ pa, float* __restrict__ out)
{
    __shared__ float sw[256];
    if (threadIdx.x < 256) sw[threadIdx.x] = w10[threadIdx.x];
    __syncthreads();
    const float slope = pa[9];
    const int row = blockIdx.x*256 + threadIdx.x;
    const float* yr = yc + (size_t)row*128;
    float a0 = 0.f, a1 = 0.f;
#pragma unroll
    for (int d = 0; d < 128; d++){
        float v = yr[d];
        a0 = fmaf(v, sw[2*d + 0], a0);
        a1 = fmaf(v, sw[2*d + 1], a1);
    }
    out[row*2 + 0] = prelu_f(a0, slope);
    out[row*2 + 1] = prelu_f(a1, slope);
}

// ---------------- host orchestration ----------------
extern "C" void kernel_launch(void* const* d_in, const int* in_sizes, int n_in,
                              void* d_out, int out_size)
{
    (void)in_sizes; (void)n_in; (void)out_size;
    const float* targets = (const float*)d_in[0];
    const float* w[10];
    for (int i = 0; i < 10; i++) w[i] = (const float*)d_in[1 + i];
    const float* pa = (const float*)d_in[11];
    float* out = (float*)d_out;

    void *px0, *px1, *px2, *px3, *pu, *pv, *pn, *pknn, *pya, *pyb, *pb7, *pbh, *pbl;
    cudaGetSymbolAddress(&px0, g_x0p);
    cudaGetSymbolAddress(&px1, g_x1);
    cudaGetSymbolAddress(&px2, g_x2);
    cudaGetSymbolAddress(&px3, g_x3);
    cudaGetSymbolAddress(&pu,  g_u);
    cudaGetSymbolAddress(&pv,  g_v);
    cudaGetSymbolAddress(&pn,  g_nrm);
    cudaGetSymbolAddress(&pknn, g_knn);
    cudaGetSymbolAddress(&pya, g_ya);
    cudaGetSymbolAddress(&pyb, g_yb);
    cudaGetSymbolAddress(&pb7, g_bias7);
    cudaGetSymbolAddress(&pbh, g_bh);
    cudaGetSymbolAddress(&pbl, g_bl);

    float* x0 = (float*)px0; float* x1 = (float*)px1;
    float* x2 = (float*)px2; float* x3 = (float*)px3;
    float* uu = (float*)pu;  float* vv = (float*)pv;
    float* nr = (float*)pn;
    int*   kn = (int*)pknn;
    float* ya = (float*)pya; float* yb = (float*)pyb;
    float* b7 = (float*)pb7;
    __nv_bfloat16* bh = (__nv_bfloat16*)pbh;
    __nv_bfloat16* bl = (__nv_bfloat16*)pbl;

    const int SM8 = (8*128*2 + 256)*4 + 128*LDD*4;
    cudaFuncSetAttribute(knn_tile_kernel<8>, cudaFuncAttributeMaxDynamicSharedMemorySize, SM8);
    cudaFuncSetAttribute(knn_hmma_kernel, cudaFuncAttributeMaxDynamicSharedMemorySize, HS_TOTAL);

    dim3 kgrid(NN/128, BB);

    // stage 0: x0p = [t,t,0,0]
    build_x0p_kernel<<<MTOT/256, 256>>>(targets);

    // stage 1 (CIN=6 via padded 8): scalar kNN
    norms_kernel<8><<<MTOT/256, 256>>>(x0, nr);
    knn_tile_kernel<8><<<kgrid, 256, SM8>>>(x0, nr, kn);
    uv_kernel<6><<<MTOT/4, 256>>>(x0, 8, w[0], uu, vv);
    edge2_kernel<<<MTOT/4, 256>>>(uu, vv, kn, w[1], pa, 0, x1);

    // stage 2: HMMA kNN on x1
    norms_kernel<64><<<MTOT/256, 256>>>(x1, nr);
    split_kernel<<<MTOT*64/256, 256>>>(x1);
    knn_hmma_kernel<<<kgrid, 256, HS_TOTAL>>>(bh, bl, nr, kn);
    uv_kernel<64><<<MTOT/4, 256>>>(x1, 64, w[2], uu, vv);
    edge2_kernel<<<MTOT/4, 256>>>(uu, vv, kn, w[3], pa, 2, x2);

    // stage 3: HMMA kNN on x2
    norms_kernel<64><<<MTOT/256, 256>>>(x2, nr);
    split_kernel<<<MTOT*64/256, 256>>>(x2);
    knn_hmma_kernel<<<kgrid, 256, HS_TOTAL>>>(bh, bl, nr, kn);
    uv_kernel<64><<<MTOT/4, 256>>>(x2, 64, w[4], uu, vv);
    edge1_kernel<<<MTOT/4, 256>>>(uu, vv, kn, pa, 4, x3);

    // head
    init_x5max_kernel<<<(BB*1024 + 255)/256, 256>>>();
    gemm192_kernel<true><<<dim3(1024/64, MTOT/64), 256>>>(
        x1, x2, x3, w[5], 1024, nullptr, nullptr, 0, pa, 5);
    bias7_kernel<<<BB, 256>>>(w[6]);
    gemm192_kernel<false><<<dim3(256/64, MTOT/64), 256>>>(
        x1, x2, x3, w[6], 256, b7, ya, 256, pa, 6);
    gemm_kernel<<<dim3(256/64, MTOT/64), 256>>>(ya, 256, w[7], 256, 256, yb, 256, pa, 7);
    gemm_kernel<<<dim3(128/64, MTOT/64), 256>>>(yb, 256, w[8], 128, 256, ya, 128, pa, 8);
    head_out_kernel<<<MTOT/256, 256>>>(ya, w[9], pa, out);
}

// round 9
// speedup vs baseline: 1.7483x; 1.0663x over previous
#include <cuda_runtime.h>
#include <cuda_bf16.h>
#include <cfloat>
#include <cstdint>
#include <math.h>

#define BB 4
#define NN 8192
#define KNN 10
#define MTOT (BB*NN)
#define LDD 129    // padded row stride of distance tile (scalar knn)
#define LDD2 130   // padded row stride of distance tile (hmma knn)
#define PADK 72    // bf16 per smem row (64 data + 8 pad) -> conflict-free ldmatrix

// ---------------- scratch (device globals; no allocation allowed) ----------------
__device__ float         g_x0p[MTOT*8];
__device__ float         g_x1[MTOT*64];
__device__ float         g_x2[MTOT*64];
__device__ float         g_x3[MTOT*64];
__device__ float         g_u[MTOT*64];
__device__ float         g_v[MTOT*64];
__device__ float         g_nrm[MTOT];
__device__ int           g_knn[MTOT*KNN];
__device__ unsigned      g_x5max[BB*1024];
__device__ float         g_bias7[BB*256];
__device__ float         g_ya[MTOT*256];
__device__ float         g_yb[MTOT*256];
__device__ __nv_bfloat16 g_bh[MTOT*64];
__device__ __nv_bfloat16 g_bl[MTOT*64];

// ---------------- helpers ----------------
__device__ __forceinline__ float prelu_f(float v, float a){ return v >= 0.f ? v : a*v; }

__device__ __forceinline__ unsigned enc_f(float f){
    unsigned u = __float_as_uint(f);
    return (u & 0x80000000u) ? ~u : (u | 0x80000000u);
}
__device__ __forceinline__ float dec_f(unsigned u){
    return (u & 0x80000000u) ? __uint_as_float(u & 0x7fffffffu) : __uint_as_float(~u);
}

__device__ __forceinline__ void topk_insert(float (&dist)[KNN], int (&idx)[KNN], float d, int j){
    if (d < dist[KNN-1]){
        float cd = d; int cj = j;
#pragma unroll
        for (int p = 0; p < KNN; p++){
            if (cd < dist[p]){
                float td = dist[p]; int tj = idx[p];
                dist[p] = cd; idx[p] = cj;
                cd = td; cj = tj;
            }
        }
    }
}

__device__ __forceinline__ uint32_t smem_u32(const void* p){
    uint32_t a;
    asm("{ .reg .u64 t; cvta.to.shared.u64 t, %1; cvt.u32.u64 %0, t; }" : "=r"(a) : "l"(p));
    return a;
}
__device__ __forceinline__ void ldsm_x4(uint32_t& r0, uint32_t& r1, uint32_t& r2, uint32_t& r3, uint32_t addr){
    asm volatile("ldmatrix.sync.aligned.m8n8.x4.shared.b16 {%0,%1,%2,%3}, [%4];"
                 : "=r"(r0), "=r"(r1), "=r"(r2), "=r"(r3) : "r"(addr));
}
__device__ __forceinline__ void mma16816(float& c0, float& c1, float& c2, float& c3,
                                         uint32_t a0, uint32_t a1, uint32_t a2, uint32_t a3,
                                         uint32_t b0, uint32_t b1){
    asm volatile(
        "mma.sync.aligned.m16n8k16.row.col.f32.bf16.bf16.f32 "
        "{%0,%1,%2,%3}, {%4,%5,%6,%7}, {%8,%9}, {%0,%1,%2,%3};"
        : "+f"(c0), "+f"(c1), "+f"(c2), "+f"(c3)
        : "r"(a0), "r"(a1), "r"(a2), "r"(a3), "r"(b0), "r"(b1));
}

// ---------------- build x0p = [t,t,0,0] padded to 8 ----------------
__global__ __launch_bounds__(256) void build_x0p_kernel(const float* __restrict__ t){
    int i = blockIdx.x*256 + threadIdx.x;
    float t0 = t[i*3+0], t1 = t[i*3+1], t2 = t[i*3+2];
    float4* o = (float4*)(g_x0p + (size_t)i*8);
    o[0] = make_float4(t0, t1, t2, t0);
    o[1] = make_float4(t1, t2, 0.f, 0.f);
}

// ---------------- row squared norms ----------------
template<int KCH>
__global__ __launch_bounds__(256) void norms_kernel(const float* __restrict__ x, float* __restrict__ nrm){
    int r = blockIdx.x*256 + threadIdx.x;
    const float* xr = x + (size_t)r*KCH;
    float s = 0.f;
#pragma unroll
    for (int k = 0; k < KCH; k++) s = fmaf(xr[k], xr[k], s);
    nrm[r] = s;
}

// ---------------- bf16 hi/lo split ----------------
__global__ __launch_bounds__(256) void split_kernel(const float* __restrict__ x){
    int i = blockIdx.x*256 + threadIdx.x;
    float f = x[i];
    __nv_bfloat16 h = __float2bfloat16(f);
    float r = f - __bfloat162float(h);
    g_bh[i] = h;
    g_bl[i] = __float2bfloat16(r);
}

// ---------------- scalar kNN (stage 1, C=8 padded) ----------------
template<int KCH>
__global__ __launch_bounds__(256, 1) void knn_tile_kernel(
    const float* __restrict__ x, const float* __restrict__ nrm, int* __restrict__ knnout)
{
    extern __shared__ float sm[];
    float* Qs = sm;
    float* Cs = Qs + KCH*128;
    float* qn = Cs + KCH*128;
    float* cn = qn + 128;
    float* D  = cn + 128;

    const int tid = threadIdx.x;
    const int b   = blockIdx.y;
    const int q0  = blockIdx.x*128;
    const float* xb = x + (size_t)b*NN*KCH;
    const float* nb = nrm + (size_t)b*NN;

    constexpr int NV = 128*(KCH/4);
    for (int f = tid; f < NV; f += 256){
        int row = f & 127;
        int kq  = (f >> 7) * 4;
        float4 v = *(const float4*)&xb[(size_t)(q0+row)*KCH + kq];
        Qs[(kq+0)*128+row]=v.x; Qs[(kq+1)*128+row]=v.y;
        Qs[(kq+2)*128+row]=v.z; Qs[(kq+3)*128+row]=v.w;
    }
    if (tid < 128) qn[tid] = nb[q0 + tid];

    float dist[KNN]; int idx[KNN];
#pragma unroll
    for (int i = 0; i < KNN; i++){ dist[i] = FLT_MAX; idx[i] = 0x7fffffff; }

    const int ty = tid >> 4;
    const int tx = tid & 15;
    int rr[8], cc[8];
#pragma unroll
    for (int i = 0; i < 4; i++){ rr[i] = ty*4 + i; rr[i+4] = 64 + ty*4 + i; }
#pragma unroll
    for (int j = 0; j < 4; j++){ cc[j] = tx*4 + j; cc[j+4] = 64 + tx*4 + j; }
    const int qh = tid & 127;
    const int hh = tid >> 7;

    for (int ct = 0; ct < NN; ct += 128){
        __syncthreads();
        for (int f = tid; f < NV; f += 256){
            int row = f & 127;
            int kq  = (f >> 7) * 4;
            float4 v = *(const float4*)&xb[(size_t)(ct+row)*KCH + kq];
            Cs[(kq+0)*128+row]=v.x; Cs[(kq+1)*128+row]=v.y;
            Cs[(kq+2)*128+row]=v.z; Cs[(kq+3)*128+row]=v.w;
        }
        if (tid < 128) cn[tid] = nb[ct + tid];
        __syncthreads();

        float acc[8][8];
#pragma unroll
        for (int i = 0; i < 8; i++)
#pragma unroll
            for (int j = 0; j < 8; j++) acc[i][j] = 0.f;

#pragma unroll 8
        for (int k = 0; k < KCH; k++){
            float a[8], bb[8];
            *(float4*)&a[0]  = *(const float4*)&Qs[k*128 + ty*4];
            *(float4*)&a[4]  = *(const float4*)&Qs[k*128 + 64 + ty*4];
            *(float4*)&bb[0] = *(const float4*)&Cs[k*128 + tx*4];
            *(float4*)&bb[4] = *(const float4*)&Cs[k*128 + 64 + tx*4];
#pragma unroll
            for (int i = 0; i < 8; i++)
#pragma unroll
                for (int j = 0; j < 8; j++) acc[i][j] = fmaf(a[i], bb[j], acc[i][j]);
        }

        float qv[8], cv[8];
#pragma unroll
        for (int i = 0; i < 8; i++) qv[i] = qn[rr[i]];
#pragma unroll
        for (int j = 0; j < 8; j++) cv[j] = cn[cc[j]];
#pragma unroll
        for (int i = 0; i < 8; i++)
#pragma unroll
            for (int j = 0; j < 8; j++)
                D[rr[i]*LDD + cc[j]] = (qv[i] + cv[j]) - 2.f*acc[i][j];
        __syncthreads();

        const float* drow = &D[qh*LDD + hh*64];
        const int cbase = ct + hh*64;
#pragma unroll 4
        for (int i = 0; i < 64; i++)
            topk_insert(dist, idx, drow[i], cbase + i);
    }

    __syncthreads();
    float* Ld = D;
    int*   Li = (int*)(D + 4096);
#pragma unroll
    for (int i = 0; i < KNN; i++){ Ld[tid*KNN + i] = dist[i]; Li[tid*KNN + i] = idx[i]; }
    __syncthreads();
    if (tid < 128){
        const float* da = &Ld[tid*KNN];        const int* ja = &Li[tid*KNN];
        const float* db = &Ld[(tid+128)*KNN];  const int* jb = &Li[(tid+128)*KNN];
        int* ko = knnout + ((size_t)b*NN + q0 + tid)*KNN;
        int ia = 0, ib = 0;
#pragma unroll
        for (int i = 0; i < KNN; i++){
            float d0 = da[ia], d1 = db[ib];
            int   j0 = ja[ia], j1 = jb[ib];
            bool A = (d0 < d1) || (d0 == d1 && j0 < j1);
            ko[i] = A ? j0 : j1;
            if (A) ia++; else ib++;
        }
    }
}

// ---------------- kNN via warp HMMA bf16-split (C=64 stages) — validated R8 ----------------
#define HS_AH 0
#define HS_AL 18432
#define HS_BH 36864
#define HS_BL 55296
#define HS_QN 73728
#define HS_CN 74240
#define HS_D  74752
#define HS_TOTAL (74752 + 128*LDD2*4)   // 141312

__global__ __launch_bounds__(256, 1) void knn_hmma_kernel(
    const __nv_bfloat16* __restrict__ xh, const __nv_bfloat16* __restrict__ xl,
    const float* __restrict__ nrm, int* __restrict__ knnout)
{
    extern __shared__ char smp[];
    const uint32_t sbase = smem_u32(smp);

    const int tid = threadIdx.x;
    const int w   = tid >> 5;
    const int l   = tid & 31;
    const int b   = blockIdx.y;
    const int q0  = blockIdx.x*128;
    const size_t rowbase = (size_t)b*NN;
    const __nv_bfloat16* xhb = xh + rowbase*64;
    const __nv_bfloat16* xlb = xl + rowbase*64;
    const float* nb = nrm + rowbase;

    float* qn = (float*)(smp + HS_QN);
    float* cn = (float*)(smp + HS_CN);
    float* D  = (float*)(smp + HS_D);

    const int lq  = l >> 3;
    const int lr  = l & 7;
    const int rowq = ((lq & 1) << 3) + lr;
    const int colq = (lq >> 1) << 3;

    for (int f = tid; f < 128*8; f += 256){
        int row = f >> 3, seg = f & 7;
        uint32_t dst = row*PADK*2 + seg*16;
        *(uint4*)(smp + HS_AH + dst) = *(const uint4*)&xhb[(size_t)(q0+row)*64 + seg*8];
        *(uint4*)(smp + HS_AL + dst) = *(const uint4*)&xlb[(size_t)(q0+row)*64 + seg*8];
    }
    if (tid < 128) qn[tid] = nb[q0 + tid];

    float dist[KNN]; int idx[KNN];
#pragma unroll
    for (int i = 0; i < KNN; i++){ dist[i] = FLT_MAX; idx[i] = 0x7fffffff; }

    const uint32_t aArow = sbase + (uint32_t)((w*16 + rowq)*PADK + colq)*2;
    const int qh = tid & 127;
    const int hh = tid >> 7;

    for (int ct = 0; ct < NN; ct += 128){
        __syncthreads();
        for (int f = tid; f < 128*8; f += 256){
            int row = f >> 3, seg = f & 7;
            uint32_t dst = row*PADK*2 + seg*16;
            *(uint4*)(smp + HS_BH + dst) = *(const uint4*)&xhb[(size_t)(ct+row)*64 + seg*8];
            *(uint4*)(smp + HS_BL + dst) = *(const uint4*)&xlb[(size_t)(ct+row)*64 + seg*8];
        }
        if (tid < 128) cn[tid] = nb[ct + tid];
        __syncthreads();

        float acc[16][4];
#pragma unroll
        for (int t = 0; t < 16; t++)
#pragma unroll
            for (int j = 0; j < 4; j++) acc[t][j] = 0.f;

#pragma unroll
        for (int kc = 0; kc < 4; kc++){
            uint32_t ah0, ah1, ah2, ah3, al0, al1, al2, al3;
            ldsm_x4(ah0, ah1, ah2, ah3, aArow + HS_AH + kc*32);
            ldsm_x4(al0, al1, al2, al3, aArow + HS_AL + kc*32);
#pragma unroll
            for (int p = 0; p < 8; p++){
                uint32_t bb = sbase + (uint32_t)((p*16 + rowq)*PADK + colq)*2 + kc*32;
                uint32_t bh0, bh1, bh2, bh3, bl0, bl1, bl2, bl3;
                ldsm_x4(bh0, bh1, bh2, bh3, bb + HS_BH);
                ldsm_x4(bl0, bl1, bl2, bl3, bb + HS_BL);
                float* c0 = acc[2*p];
                float* c1 = acc[2*p+1];
                mma16816(c0[0], c0[1], c0[2], c0[3], ah0, ah1, ah2, ah3, bh0, bh2);
                mma16816(c1[0], c1[1], c1[2], c1[3], ah0, ah1, ah2, ah3, bh1, bh3);
                mma16816(c0[0], c0[1], c0[2], c0[3], ah0, ah1, ah2, ah3, bl0, bl2);
                mma16816(c1[0], c1[1], c1[2], c1[3], ah0, ah1, ah2, ah3, bl1, bl3);
                mma16816(c0[0], c0[1], c0[2], c0[3], al0, al1, al2, al3, bh0, bh2);
                mma16816(c1[0], c1[1], c1[2], c1[3], al0, al1, al2, al3, bh1, bh3);
            }
        }

        {
            const int r0 = w*16 + (l >> 2);
            const float qn0 = qn[r0], qn1 = qn[r0 + 8];
#pragma unroll
            for (int t = 0; t < 16; t++){
                int c = t*8 + (l & 3)*2;
                float c0 = cn[c], c1 = cn[c+1];
                *(float2*)&D[r0*LDD2 + c]     = make_float2((qn0 + c0) - 2.f*acc[t][0],
                                                            (qn0 + c1) - 2.f*acc[t][1]);
                *(float2*)&D[(r0+8)*LDD2 + c] = make_float2((qn1 + c0) - 2.f*acc[t][2],
                                                            (qn1 + c1) - 2.f*acc[t][3]);
            }
        }
        __syncthreads();

        const float* drow = &D[qh*LDD2 + hh*64];
        const int cbase = ct + hh*64;
#pragma unroll 4
        for (int i = 0; i < 64; i++)
            topk_insert(dist, idx, drow[i], cbase + i);
    }

    __syncthreads();
    float* Ld = D;
    int*   Li = (int*)(D + 4096);
#pragma unroll
    for (int i = 0; i < KNN; i++){ Ld[tid*KNN + i] = dist[i]; Li[tid*KNN + i] = idx[i]; }
    __syncthreads();
    if (tid < 128){
        const float* da = &Ld[tid*KNN];        const int* ja = &Li[tid*KNN];
        const float* db = &Ld[(tid+128)*KNN];  const int* jb = &Li[(tid+128)*KNN];
        int* ko = knnout + (rowbase + q0 + tid)*KNN;
        int ia = 0, ib = 0;
#pragma unroll
        for (int i = 0; i < KNN; i++){
            float d0 = da[ia], d1 = db[ib];
            int   j0 = ja[ia], j1 = jb[ib];
            bool A = (d0 < d1) || (d0 == d1 && j0 < j1);
            ko[i] = A ? j0 : j1;
            if (A) ia++; else ib++;
        }
    }
}

// ---------------- uv precompute: v = x@Wa, u = x@(Wb - Wa) ----------------
template<int CIN>
__global__ __launch_bounds__(256) void uv_kernel(
    const float* __restrict__ x, int xs, const float* __restrict__ w,
    float* __restrict__ u, float* __restrict__ v)
{
    __shared__ float sW1[CIN*64];
    __shared__ float sW2[CIN*64];
    __shared__ float sx[4][CIN];
    const int tid = threadIdx.x;
    const int p = tid >> 6, c = tid & 63;
    for (int i = tid; i < CIN*64; i += 256){
        float a = w[i];
        sW1[i] = a;
        sW2[i] = w[CIN*64 + i] - a;
    }
    const int gp = blockIdx.x*4 + p;
    for (int i = c; i < CIN; i += 64) sx[p][i] = x[(size_t)gp*xs + i];
    __syncthreads();
    float uu = 0.f, vv = 0.f;
#pragma unroll
    for (int d = 0; d < CIN; d++){
        float xv = sx[p][d];
        vv = fmaf(xv, sW1[d*64 + c], vv);
        uu = fmaf(xv, sW2[d*64 + c], uu);
    }
    u[(size_t)gp*64 + c] = uu;
    v[(size_t)gp*64 + c] = vv;
}

// ---------------- 2-layer edgeconv tail ----------------
__global__ __launch_bounds__(256) void edge2_kernel(
    const float* __restrict__ u, const float* __restrict__ v,
    const int* __restrict__ knn, const float* __restrict__ w2,
    const float* __restrict__ pa, int ia, float* __restrict__ out)
{
    __shared__ float sh1[4][64];
    const int tid = threadIdx.x;
    const int p = tid >> 6, c = tid & 63;
    float wcol[64];
#pragma unroll
    for (int d = 0; d < 64; d++) wcol[d] = __ldg(&w2[d*64 + c]);
    const float a1 = pa[ia], a2 = pa[ia+1];
    const int gp = blockIdx.x*4 + p;
    const int b  = gp >> 13;
    const float* vb = v + (size_t)b*NN*64;
    const float ur = u[(size_t)gp*64 + c];
    const int* krow = knn + (size_t)gp*KNN;
    float maxv = -FLT_MAX;
#pragma unroll
    for (int kk = 0; kk < KNN; kk++){
        int j = krow[kk];
        float h = prelu_f(ur + vb[(size_t)j*64 + c], a1);
        __syncthreads();
        sh1[p][c] = h;
        __syncthreads();
        float acc = 0.f;
#pragma unroll
        for (int d = 0; d < 64; d += 4){
            float4 hv = *(const float4*)&sh1[p][d];
            acc = fmaf(hv.x, wcol[d+0], acc);
            acc = fmaf(hv.y, wcol[d+1], acc);
            acc = fmaf(hv.z, wcol[d+2], acc);
            acc = fmaf(hv.w, wcol[d+3], acc);
        }
        maxv = fmaxf(maxv, prelu_f(acc, a2));
    }
    out[(size_t)gp*64 + c] = maxv;
}

// ---------------- 1-layer edgeconv tail ----------------
__global__ __launch_bounds__(256) void edge1_kernel(
    const float* __restrict__ u, const float* __restrict__ v,
    const int* __restrict__ knn, const float* __restrict__ pa, int ia,
    float* __restrict__ out)
{
    const int tid = threadIdx.x;
    const int p = tid >> 6, c = tid & 63;
    const float a1 = pa[ia];
    const int gp = blockIdx.x*4 + p;
    const int b  = gp >> 13;
    const float* vb = v + (size_t)b*NN*64;
    const float ur = u[(size_t)gp*64 + c];
    const int* krow = knn + (size_t)gp*KNN;
    float maxv = -FLT_MAX;
#pragma unroll
    for (int kk = 0; kk < KNN; kk++){
        int j = krow[kk];
        maxv = fmaxf(maxv, prelu_f(ur + vb[(size_t)j*64 + c], a1));
    }
    out[(size_t)gp*64 + c] = maxv;
}

// ---------------- init x5max ----------------
__global__ void init_x5max_kernel(){
    int i = blockIdx.x*256 + threadIdx.x;
    if (i < BB*1024) g_x5max[i] = 0u;
}

// ---------------- HMMA bf16-split GEMM: C = prelu(A @ W (+bias)) or colmax ----------------
// Tile M=128 x N=64, 256 threads / 8 warps; warp w owns rows w*16..+15, all 64 cols.
// W tile split+transposed to [n][k] smem once per block; A chunks split on the fly.
template<int Kd, bool GATHER, bool COLMAX>
__global__ __launch_bounds__(256) void hmma_gemm_kernel(
    const float* __restrict__ A1, const float* __restrict__ A2, const float* __restrict__ A3,
    int lda, const float* __restrict__ W, int Nc,
    const float* __restrict__ bias, float* __restrict__ Cout, int ldc,
    const float* __restrict__ pa, int ia)
{
    constexpr int PADW = Kd + 8;
    constexpr int PADA = 24;
    constexpr int OFF_WH = 0;
    constexpr int OFF_WL = 64*PADW*2;
    constexpr int OFF_AH = 2*OFF_WL;
    constexpr int OFF_AL = OFF_AH + 128*PADA*2;
    constexpr int OFF_SMAX = OFF_AL + 128*PADA*2;

    extern __shared__ char smp[];
    const uint32_t sbase = smem_u32(smp);
    __nv_bfloat16* Wh = (__nv_bfloat16*)(smp + OFF_WH);
    __nv_bfloat16* Wl = (__nv_bfloat16*)(smp + OFF_WL);
    __nv_bfloat16* Ah = (__nv_bfloat16*)(smp + OFF_AH);
    __nv_bfloat16* Al = (__nv_bfloat16*)(smp + OFF_AL);
    float* smax = (float*)(smp + OFF_SMAX);

    const int tid = threadIdx.x;
    const int w   = tid >> 5;
    const int l   = tid & 31;
    const int col0 = blockIdx.x*64;
    const int row0 = blockIdx.y*128;
    const int b = row0 >> 13;
    const float slope = pa[ia];

    // stage W tile: split + transpose to [n][k]
    for (int idx = tid; idx < Kd*64; idx += 256){
        int k = idx >> 6, n = idx & 63;
        float f = W[(size_t)k*Nc + col0 + n];
        __nv_bfloat16 h = __float2bfloat16(f);
        Wh[n*PADW + k] = h;
        Wl[n*PADW + k] = __float2bfloat16(f - __bfloat162float(h));
    }

    const int lq  = l >> 3;
    const int lr  = l & 7;
    const int rowq = ((lq & 1) << 3) + lr;
    const int colq = (lq >> 1) << 3;

    const uint32_t aAh = sbase + OFF_AH + (uint32_t)((w*16 + rowq)*PADA + colq)*2;
    const uint32_t aAl = sbase + OFF_AL + (uint32_t)((w*16 + rowq)*PADA + colq)*2;

    float acc[8][4];
#pragma unroll
    for (int f = 0; f < 8; f++)
#pragma unroll
        for (int j = 0; j < 4; j++) acc[f][j] = 0.f;

#pragma unroll 2
    for (int chunk = 0; chunk < Kd/16; chunk++){
        __syncthreads();   // W staged (iter 0) / prior A consumers done
        const int k0 = chunk*16;
        const float* src; int koff; int ld;
        if (GATHER){
            if (k0 < 64)      { src = A1; koff = k0;       }
            else if (k0 < 128){ src = A2; koff = k0 - 64;  }
            else              { src = A3; koff = k0 - 128; }
            ld = 64;
        } else { src = A1; koff = k0; ld = lda; }

        for (int it = tid; it < 512; it += 256){
            int row = it >> 2, kq = (it & 3)*4;
            float4 v = *(const float4*)&src[(size_t)(row0 + row)*ld + koff + kq];
            __nv_bfloat16 h0 = __float2bfloat16(v.x);
            __nv_bfloat16 h1 = __float2bfloat16(v.y);
            __nv_bfloat16 h2 = __float2bfloat16(v.z);
            __nv_bfloat16 h3 = __float2bfloat16(v.w);
            __nv_bfloat16* ph = &Ah[row*PADA + kq];
            __nv_bfloat16* pl = &Al[row*PADA + kq];
            ph[0]=h0; ph[1]=h1; ph[2]=h2; ph[3]=h3;
            pl[0]=__float2bfloat16(v.x - __bfloat162float(h0));
            pl[1]=__float2bfloat16(v.y - __bfloat162float(h1));
            pl[2]=__float2bfloat16(v.z - __bfloat162float(h2));
            pl[3]=__float2bfloat16(v.w - __bfloat162float(h3));
        }
        __syncthreads();

        uint32_t ah0, ah1, ah2, ah3, al0, al1, al2, al3;
        ldsm_x4(ah0, ah1, ah2, ah3, aAh);
        ldsm_x4(al0, al1, al2, al3, aAl);
#pragma unroll
        for (int p = 0; p < 4; p++){
            uint32_t roff = (uint32_t)((p*16 + rowq)*PADW + k0 + colq)*2;
            uint32_t bh0, bh1, bh2, bh3, bl0, bl1, bl2, bl3;
            ldsm_x4(bh0, bh1, bh2, bh3, sbase + OFF_WH + roff);
            ldsm_x4(bl0, bl1, bl2, bl3, sbase + OFF_WL + roff);
            float* c0 = acc[2*p];
            float* c1 = acc[2*p+1];
            mma16816(c0[0], c0[1], c0[2], c0[3], ah0, ah1, ah2, ah3, bh0, bh2);
            mma16816(c1[0], c1[1], c1[2], c1[3], ah0, ah1, ah2, ah3, bh1, bh3);
            mma16816(c0[0], c0[1], c0[2], c0[3], ah0, ah1, ah2, ah3, bl0, bl2);
            mma16816(c1[0], c1[1], c1[2], c1[3], ah0, ah1, ah2, ah3, bl1, bl3);
            mma16816(c0[0], c0[1], c0[2], c0[3], al0, al1, al2, al3, bh0, bh2);
            mma16816(c1[0], c1[1], c1[2], c1[3], al0, al1, al2, al3, bh1, bh3);
        }
    }

    if (!COLMAX){
        const int r0 = w*16 + (l >> 2);
#pragma unroll
        for (int p = 0; p < 4; p++){
#pragma unroll
            for (int j = 0; j < 2; j++){
                const float* cc = acc[2*p + j];
                int col = p*16 + j*8 + (l & 3)*2;
                float b0 = bias ? bias[b*Nc + col0 + col]     : 0.f;
                float b1 = bias ? bias[b*Nc + col0 + col + 1] : 0.f;
                *(float2*)&Cout[(size_t)(row0 + r0)*ldc + col0 + col] =
                    make_float2(prelu_f(cc[0] + b0, slope), prelu_f(cc[1] + b1, slope));
                *(float2*)&Cout[(size_t)(row0 + r0 + 8)*ldc + col0 + col] =
                    make_float2(prelu_f(cc[2] + b0, slope), prelu_f(cc[3] + b1, slope));
            }
        }
    } else {
        // colmax: reduce over 16 warp rows via shfl (lanes l^4,l^8,l^16 share cols), then across warps
#pragma unroll
        for (int p = 0; p < 4; p++){
#pragma unroll
            for (int j = 0; j < 2; j++){
                const float* cc = acc[2*p + j];
                float m0 = fmaxf(cc[0], cc[2]);
                float m1 = fmaxf(cc[1], cc[3]);
#pragma unroll
                for (int s = 4; s <= 16; s <<= 1){
                    m0 = fmaxf(m0, __shfl_xor_sync(0xffffffffu, m0, s));
                    m1 = fmaxf(m1, __shfl_xor_sync(0xffffffffu, m1, s));
                }
                if (l < 4){
                    int col = p*16 + j*8 + l*2;
                    smax[w*64 + col]     = m0;
                    smax[w*64 + col + 1] = m1;
                }
            }
        }
        __syncthreads();
        if (tid < 64){
            float mm = smax[tid];
#pragma unroll
            for (int t = 1; t < 8; t++) mm = fmaxf(mm, smax[t*64 + tid]);
            atomicMax(&g_x5max[b*1024 + col0 + tid], enc_f(prelu_f(mm, slope)));
        }
    }
}

// host-side smem size for hmma_gemm
static inline int hg_smem(int Kd){
    int padw = Kd + 8;
    return 2*(64*padw*2) + 2*(128*24*2) + 8*64*4;
}

// ---------------- bias7 ----------------
__global__ __launch_bounds__(256) void bias7_kernel(const float* __restrict__ w7){
    int b = blockIdx.x, c = threadIdx.x;
    float acc = 0.f;
    for (int d = 0; d < 1024; d++){
        float v = dec_f(g_x5max[b*1024 + d]);
        acc = fmaf(v, w7[(size_t)(192 + d)*256 + c], acc);
    }
    g_bias7[b*256 + c] = acc;
}

// ---------------- final layer ----------------
__global__ __launch_bounds__(256) void head_out_kernel(
    const float* __restrict__ yc, const float* __restrict__ w10,
    const float* __restrict__ pa, float* __restrict__ out)
{
    __shared__ float sw[256];
    if (threadIdx.x < 256) sw[threadIdx.x] = w10[threadIdx.x];
    __syncthreads();
    const float slope = pa[9];
    const int row = blockIdx.x*256 + threadIdx.x;
    const float* yr = yc + (size_t)row*128;
    float a0 = 0.f, a1 = 0.f;
#pragma unroll
    for (int d = 0; d < 128; d++){
        float v = yr[d];
        a0 = fmaf(v, sw[2*d + 0], a0);
        a1 = fmaf(v, sw[2*d + 1], a1);
    }
    out[row*2 + 0] = prelu_f(a0, slope);
    out[row*2 + 1] = prelu_f(a1, slope);
}

// ---------------- host orchestration ----------------
extern "C" void kernel_launch(void* const* d_in, const int* in_sizes, int n_in,
                              void* d_out, int out_size)
{
    (void)in_sizes; (void)n_in; (void)out_size;
    const float* targets = (const float*)d_in[0];
    const float* w[10];
    for (int i = 0; i < 10; i++) w[i] = (const float*)d_in[1 + i];
    const float* pa = (const float*)d_in[11];
    float* out = (float*)d_out;

    void *px0, *px1, *px2, *px3, *pu, *pv, *pn, *pknn, *pya, *pyb, *pb7, *pbh, *pbl;
    cudaGetSymbolAddress(&px0, g_x0p);
    cudaGetSymbolAddress(&px1, g_x1);
    cudaGetSymbolAddress(&px2, g_x2);
    cudaGetSymbolAddress(&px3, g_x3);
    cudaGetSymbolAddress(&pu,  g_u);
    cudaGetSymbolAddress(&pv,  g_v);
    cudaGetSymbolAddress(&pn,  g_nrm);
    cudaGetSymbolAddress(&pknn, g_knn);
    cudaGetSymbolAddress(&pya, g_ya);
    cudaGetSymbolAddress(&pyb, g_yb);
    cudaGetSymbolAddress(&pb7, g_bias7);
    cudaGetSymbolAddress(&pbh, g_bh);
    cudaGetSymbolAddress(&pbl, g_bl);

    float* x0 = (float*)px0; float* x1 = (float*)px1;
    float* x2 = (float*)px2; float* x3 = (float*)px3;
    float* uu = (float*)pu;  float* vv = (float*)pv;
    float* nr = (float*)pn;
    int*   kn = (int*)pknn;
    float* ya = (float*)pya; float* yb = (float*)pyb;
    float* b7 = (float*)pb7;
    __nv_bfloat16* bh = (__nv_bfloat16*)pbh;
    __nv_bfloat16* bl = (__nv_bfloat16*)pbl;

    const int SM8 = (8*128*2 + 256)*4 + 128*LDD*4;
    cudaFuncSetAttribute(knn_tile_kernel<8>, cudaFuncAttributeMaxDynamicSharedMemorySize, SM8);
    cudaFuncSetAttribute(knn_hmma_kernel, cudaFuncAttributeMaxDynamicSharedMemorySize, HS_TOTAL);
    cudaFuncSetAttribute(hmma_gemm_kernel<192,true,true>,   cudaFuncAttributeMaxDynamicSharedMemorySize, hg_smem(192));
    cudaFuncSetAttribute(hmma_gemm_kernel<192,true,false>,  cudaFuncAttributeMaxDynamicSharedMemorySize, hg_smem(192));
    cudaFuncSetAttribute(hmma_gemm_kernel<256,false,false>, cudaFuncAttributeMaxDynamicSharedMemorySize, hg_smem(256));

    dim3 kgrid(NN/128, BB);

    // stage 0: x0p = [t,t,0,0]
    build_x0p_kernel<<<MTOT/256, 256>>>(targets);

    // stage 1 (CIN=6 via padded 8): scalar kNN
    norms_kernel<8><<<MTOT/256, 256>>>(x0, nr);
    knn_tile_kernel<8><<<kgrid, 256, SM8>>>(x0, nr, kn);
    uv_kernel<6><<<MTOT/4, 256>>>(x0, 8, w[0], uu, vv);
    edge2_kernel<<<MTOT/4, 256>>>(uu, vv, kn, w[1], pa, 0, x1);

    // stage 2: HMMA kNN on x1
    norms_kernel<64><<<MTOT/256, 256>>>(x1, nr);
    split_kernel<<<MTOT*64/256, 256>>>(x1);
    knn_hmma_kernel<<<kgrid, 256, HS_TOTAL>>>(bh, bl, nr, kn);
    uv_kernel<64><<<MTOT/4, 256>>>(x1, 64, w[2], uu, vv);
    edge2_kernel<<<MTOT/4, 256>>>(uu, vv, kn, w[3], pa, 2, x2);

    // stage 3: HMMA kNN on x2
    norms_kernel<64><<<MTOT/256, 256>>>(x2, nr);
    split_kernel<<<MTOT*64/256, 256>>>(x2);
    knn_hmma_kernel<<<kgrid, 256, HS_TOTAL>>>(bh, bl, nr, kn);
    uv_kernel<64><<<MTOT/4, 256>>>(x2, 64, w[4], uu, vv);
    edge1_kernel<<<MTOT/4, 256>>>(uu, vv, kn, pa, 4, x3);

    // head (all HMMA)
    init_x5max_kernel<<<(BB*1024 + 255)/256, 256>>>();
    hmma_gemm_kernel<192,true,true><<<dim3(1024/64, MTOT/128), 256, hg_smem(192)>>>(
        x1, x2, x3, 64, w[5], 1024, nullptr, nullptr, 0, pa, 5);
    bias7_kernel<<<BB, 256>>>(w[6]);
    hmma_gemm_kernel<192,true,false><<<dim3(256/64, MTOT/128), 256, hg_smem(192)>>>(
        x1, x2, x3, 64, w[6], 256, b7, ya, 256, pa, 6);
    hmma_gemm_kernel<256,false,false><<<dim3(256/64, MTOT/128), 256, hg_smem(256)>>>(
        ya, nullptr, nullptr, 256, w[7], 256, nullptr, yb, 256, pa, 7);
    hmma_gemm_kernel<256,false,false><<<dim3(128/64, MTOT/128), 256, hg_smem(256)>>>(
        yb, nullptr, nullptr, 256, w[8], 128, nullptr, ya, 128, pa, 8);
    head_out_kernel<<<MTOT/256, 256>>>(ya, w[9], pa, out);
}

// round 11
// speedup vs baseline: 2.0881x; 1.1944x over previous
#include <cuda_runtime.h>
#include <cuda_bf16.h>
#include <cfloat>
#include <cstdint>
#include <math.h>

#define BB 4
#define NN 8192
#define KNN 10
#define MTOT (BB*NN)
#define LDD2R 132  // padded row stride of distance tile (16B-aligned rows, conflict-free LDS.128)

// ---------------- scratch (device globals; no allocation allowed) ----------------
__device__ float         g_x0p[MTOT*8];
__device__ float         g_x1[MTOT*64];
__device__ float         g_x2[MTOT*64];
__device__ float         g_x3[MTOT*64];
__device__ float         g_u[MTOT*64];
__device__ float         g_v[MTOT*64];
__device__ float         g_nrm[MTOT];
__device__ int           g_knn[MTOT*KNN];
__device__ unsigned      g_x5max[BB*1024];
__device__ float         g_bias7[BB*256];
__device__ float         g_ya[MTOT*256];
__device__ float         g_yb[MTOT*256];
__device__ __nv_bfloat16 g_bh[MTOT*64];   // bf16 hi split (also reused 16-wide for stage 1)
__device__ __nv_bfloat16 g_bl[MTOT*64];   // bf16 lo split

// ---------------- helpers ----------------
__device__ __forceinline__ float prelu_f(float v, float a){ return v >= 0.f ? v : a*v; }

__device__ __forceinline__ unsigned enc_f(float f){
    unsigned u = __float_as_uint(f);
    return (u & 0x80000000u) ? ~u : (u | 0x80000000u);
}
__device__ __forceinline__ float dec_f(unsigned u){
    return (u & 0x80000000u) ? __uint_as_float(u & 0x7fffffffu) : __uint_as_float(~u);
}

__device__ __forceinline__ void topk_insert(float (&dist)[KNN], int (&idx)[KNN], float d, int j){
    if (d < dist[KNN-1]){
        float cd = d; int cj = j;
#pragma unroll
        for (int p = 0; p < KNN; p++){
            if (cd < dist[p]){
                float td = dist[p]; int tj = idx[p];
                dist[p] = cd; idx[p] = cj;
                cd = td; cj = tj;
            }
        }
    }
}

__device__ __forceinline__ uint32_t smem_u32(const void* p){
    uint32_t a;
    asm("{ .reg .u64 t; cvta.to.shared.u64 t, %1; cvt.u32.u64 %0, t; }" : "=r"(a) : "l"(p));
    return a;
}
__device__ __forceinline__ void ldsm_x4(uint32_t& r0, uint32_t& r1, uint32_t& r2, uint32_t& r3, uint32_t addr){
    asm volatile("ldmatrix.sync.aligned.m8n8.x4.shared.b16 {%0,%1,%2,%3}, [%4];"
                 : "=r"(r0), "=r"(r1), "=r"(r2), "=r"(r3) : "r"(addr));
}
__device__ __forceinline__ void mma16816(float& c0, float& c1, float& c2, float& c3,
                                         uint32_t a0, uint32_t a1, uint32_t a2, uint32_t a3,
                                         uint32_t b0, uint32_t b1){
    asm volatile(
        "mma.sync.aligned.m16n8k16.row.col.f32.bf16.bf16.f32 "
        "{%0,%1,%2,%3}, {%4,%5,%6,%7}, {%8,%9}, {%0,%1,%2,%3};"
        : "+f"(c0), "+f"(c1), "+f"(c2), "+f"(c3)
        : "r"(a0), "r"(a1), "r"(a2), "r"(a3), "r"(b0), "r"(b1));
}
__device__ __forceinline__ void cpa16(uint32_t dst, const void* src){
    asm volatile("cp.async.ca.shared.global [%0], [%1], 16;" :: "r"(dst), "l"(src) : "memory");
}
#define CPA_COMMIT() asm volatile("cp.async.commit_group;" ::: "memory")
#define CPA_WAIT1()  asm volatile("cp.async.wait_group 1;" ::: "memory")
#define CPA_WAIT0()  asm volatile("cp.async.wait_group 0;" ::: "memory")

// ---------------- build x0p = [t,t,0,0] padded to 8 ----------------
__global__ __launch_bounds__(256) void build_x0p_kernel(const float* __restrict__ t){
    int i = blockIdx.x*256 + threadIdx.x;
    float t0 = t[i*3+0], t1 = t[i*3+1], t2 = t[i*3+2];
    float4* o = (float4*)(g_x0p + (size_t)i*8);
    o[0] = make_float4(t0, t1, t2, t0);
    o[1] = make_float4(t1, t2, 0.f, 0.f);
}

// ---------------- row squared norms (C=64) ----------------
__global__ __launch_bounds__(256) void norms64_kernel(const float* __restrict__ x, float* __restrict__ nrm){
    int r = blockIdx.x*256 + threadIdx.x;
    const float* xr = x + (size_t)r*64;
    float s = 0.f;
#pragma unroll
    for (int k = 0; k < 64; k++) s = fmaf(xr[k], xr[k], s);
    nrm[r] = s;
}

// ---------------- bf16 hi/lo split (C=64 features) ----------------
__global__ __launch_bounds__(256) void split_kernel(const float* __restrict__ x){
    int i = blockIdx.x*256 + threadIdx.x;
    float f = x[i];
    __nv_bfloat16 h = __float2bfloat16(f);
    float r = f - __bfloat162float(h);
    g_bh[i] = h;
    g_bl[i] = __float2bfloat16(r);
}

// ---------------- stage-1: split targets (C=3) to 16-wide bf16 rows + norms ----------------
// stage-1 distances on raw targets = 0.5x the reference's 6-channel distances -> same ordering.
__global__ __launch_bounds__(256) void split3_kernel(const float* __restrict__ t){
    int i = blockIdx.x*256 + threadIdx.x;   // [0, MTOT)
    float t0 = t[i*3+0], t1 = t[i*3+1], t2 = t[i*3+2];
    g_nrm[i] = fmaf(t0, t0, fmaf(t1, t1, t2*t2));
    union { __nv_bfloat16 h[16]; uint4 v[2]; } rh, rl;
#pragma unroll
    for (int k = 0; k < 16; k++){ rh.h[k] = __float2bfloat16(0.f); rl.h[k] = __float2bfloat16(0.f); }
    float tv[3] = {t0, t1, t2};
#pragma unroll
    for (int k = 0; k < 3; k++){
        __nv_bfloat16 h = __float2bfloat16(tv[k]);
        rh.h[k] = h;
        rl.h[k] = __float2bfloat16(tv[k] - __bfloat162float(h));
    }
    uint4* oh = (uint4*)&g_bh[(size_t)i*16];
    uint4* ol = (uint4*)&g_bl[(size_t)i*16];
    oh[0] = rh.v[0]; oh[1] = rh.v[1];
    ol[0] = rl.v[0]; ol[1] = rl.v[1];
}

// ---------------- kNN via warp HMMA bf16-split, cp.async double-buffered B ----------------
// NKC = number of 16-wide k chunks (4 for C=64, 1 for C=16-padded stage 1).
// 256 threads / 8 warps; warp w owns query rows w*16..+15, all 128 candidate cols.
// dot = Ah*Bh + Ah*Bl + Al*Bh (fp32 accum); D staged to smem; 2 threads/query scan.
template<int NKC, int PADKT>
__global__ __launch_bounds__(256, 1) void knn_hmma_kernel(
    const __nv_bfloat16* __restrict__ xh, const __nv_bfloat16* __restrict__ xl,
    const float* __restrict__ nrm, int* __restrict__ knnout)
{
    constexpr int KCHB = NKC*16;         // bf16 per row
    constexpr int SEGS = NKC*2;          // 16B units per row
    constexpr int SZ_A = 128*PADKT*2;    // bytes per tile buffer
    constexpr int OFF_AH = 0;
    constexpr int OFF_AL = SZ_A;
    constexpr int OFF_B  = 2*SZ_A;       // buf b: BH = OFF_B + b*2*SZ_A, BL = +SZ_A
    constexpr int OFF_QN = 6*SZ_A;
    constexpr int OFF_CN = OFF_QN + 512; // two 512B buffers
    constexpr int OFF_D  = OFF_CN + 1024;

    extern __shared__ char smp[];
    const uint32_t sbase = smem_u32(smp);

    const int tid = threadIdx.x;
    const int w   = tid >> 5;
    const int l   = tid & 31;
    const int b   = blockIdx.y;
    const int q0  = blockIdx.x*128;
    const size_t rowbase = (size_t)b*NN;
    const __nv_bfloat16* xhb = xh + rowbase*KCHB;
    const __nv_bfloat16* xlb = xl + rowbase*KCHB;
    const float* nb = nrm + rowbase;

    float* qn = (float*)(smp + OFF_QN);
    float* D  = (float*)(smp + OFF_D);

    auto issue_tile = [&](int buf, int ct2){
        uint32_t bhb = sbase + OFF_B + (uint32_t)buf*2*SZ_A;
        uint32_t blb = bhb + SZ_A;
        for (int f = tid; f < 128*SEGS; f += 256){
            int row = f / SEGS, seg = f - row*SEGS;
            uint32_t off = (uint32_t)(row*PADKT*2 + seg*16);
            cpa16(bhb + off, (const char*)xhb + ((size_t)(ct2+row)*KCHB + seg*8)*2);
            cpa16(blb + off, (const char*)xlb + ((size_t)(ct2+row)*KCHB + seg*8)*2);
        }
        if (tid < 32) cpa16(sbase + OFF_CN + (uint32_t)buf*512 + tid*16, &nb[ct2 + tid*4]);
    };

    // prologue: start tile 0 copies; stage resident A tiles + qn with plain loads
    issue_tile(0, 0); CPA_COMMIT();
    for (int f = tid; f < 128*SEGS; f += 256){
        int row = f / SEGS, seg = f - row*SEGS;
        uint32_t off = (uint32_t)(row*PADKT*2 + seg*16);
        *(uint4*)(smp + OFF_AH + off) = *(const uint4*)&xhb[(size_t)(q0+row)*KCHB + seg*8];
        *(uint4*)(smp + OFF_AL + off) = *(const uint4*)&xlb[(size_t)(q0+row)*KCHB + seg*8];
    }
    if (tid < 128) qn[tid] = nb[q0 + tid];

    float dist[KNN]; int idx[KNN];
#pragma unroll
    for (int i = 0; i < KNN; i++){ dist[i] = FLT_MAX; idx[i] = 0x7fffffff; }

    // ldmatrix lane geometry
    const int lq  = l >> 3;
    const int lr  = l & 7;
    const int rowq = ((lq & 1) << 3) + lr;
    const int colq = (lq >> 1) << 3;
    const uint32_t aAoff = (uint32_t)((w*16 + rowq)*PADKT + colq)*2;
    const int qh = tid & 127;
    const int hh = tid >> 7;

    for (int t = 0; t < NN/128; t++){
        const int ct = t*128;
        if (t < NN/128 - 1){
            issue_tile((t+1) & 1, ct + 128); CPA_COMMIT();
            CPA_WAIT1();
        } else {
            CPA_WAIT0();
        }
        __syncthreads();   // B[t]/cn[t] visible; all threads done scanning D[t-1]

        const uint32_t bhb = sbase + OFF_B + (uint32_t)(t & 1)*2*SZ_A;
        const uint32_t blb = bhb + SZ_A;
        const float* cn = (const float*)(smp + OFF_CN + (uint32_t)(t & 1)*512);

        float acc[16][4];
#pragma unroll
        for (int f = 0; f < 16; f++)
#pragma unroll
            for (int j = 0; j < 4; j++) acc[f][j] = 0.f;

#pragma unroll
        for (int kc = 0; kc < NKC; kc++){
            uint32_t ah0, ah1, ah2, ah3, al0, al1, al2, al3;
            ldsm_x4(ah0, ah1, ah2, ah3, sbase + OFF_AH + aAoff + kc*32);
            ldsm_x4(al0, al1, al2, al3, sbase + OFF_AL + aAoff + kc*32);
#pragma unroll
            for (int p = 0; p < 8; p++){
                uint32_t roff = (uint32_t)((p*16 + rowq)*PADKT + colq)*2 + kc*32;
                uint32_t bh0, bh1, bh2, bh3, bl0, bl1, bl2, bl3;
                ldsm_x4(bh0, bh1, bh2, bh3, bhb + roff);
                ldsm_x4(bl0, bl1, bl2, bl3, blb + roff);
                float* c0 = acc[2*p];
                float* c1 = acc[2*p+1];
                mma16816(c0[0], c0[1], c0[2], c0[3], ah0, ah1, ah2, ah3, bh0, bh2);
                mma16816(c1[0], c1[1], c1[2], c1[3], ah0, ah1, ah2, ah3, bh1, bh3);
                mma16816(c0[0], c0[1], c0[2], c0[3], ah0, ah1, ah2, ah3, bl0, bl2);
                mma16816(c1[0], c1[1], c1[2], c1[3], ah0, ah1, ah2, ah3, bl1, bl3);
                mma16816(c0[0], c0[1], c0[2], c0[3], al0, al1, al2, al3, bh0, bh2);
                mma16816(c1[0], c1[1], c1[2], c1[3], al0, al1, al2, al3, bh1, bh3);
            }
        }

        // epilogue: distances into D
        {
            const int r0 = w*16 + (l >> 2);
            const float qn0 = qn[r0], qn1 = qn[r0 + 8];
#pragma unroll
            for (int p = 0; p < 16; p++){
                int c = p*8 + (l & 3)*2;
                float c0 = cn[c], c1 = cn[c+1];
                *(float2*)&D[r0*LDD2R + c]     = make_float2((qn0 + c0) - 2.f*acc[p][0],
                                                             (qn0 + c1) - 2.f*acc[p][1]);
                *(float2*)&D[(r0+8)*LDD2R + c] = make_float2((qn1 + c0) - 2.f*acc[p][2],
                                                             (qn1 + c1) - 2.f*acc[p][3]);
            }
        }
        __syncthreads();

        // topk scan: 2 threads per query, 64 candidates each, float4 loads, ascending index
        const float* drow = &D[qh*LDD2R + hh*64];
        const int cbase = ct + hh*64;
#pragma unroll 4
        for (int i = 0; i < 64; i += 4){
            float4 v = *(const float4*)&drow[i];
            topk_insert(dist, idx, v.x, cbase + i + 0);
            topk_insert(dist, idx, v.y, cbase + i + 1);
            topk_insert(dist, idx, v.z, cbase + i + 2);
            topk_insert(dist, idx, v.w, cbase + i + 3);
        }
    }

    // merge the two half-lists per query (stable, exact)
    __syncthreads();
    float* Ld = D;
    int*   Li = (int*)(D + 4096);
#pragma unroll
    for (int i = 0; i < KNN; i++){ Ld[tid*KNN + i] = dist[i]; Li[tid*KNN + i] = idx[i]; }
    __syncthreads();
    if (tid < 128){
        const float* da = &Ld[tid*KNN];        const int* ja = &Li[tid*KNN];
        const float* db = &Ld[(tid+128)*KNN];  const int* jb = &Li[(tid+128)*KNN];
        int* ko = knnout + (rowbase + q0 + tid)*KNN;
        int ia = 0, ib = 0;
#pragma unroll
        for (int i = 0; i < KNN; i++){
            float d0 = da[ia], d1 = db[ib];
            int   j0 = ja[ia], j1 = jb[ib];
            bool A = (d0 < d1) || (d0 == d1 && j0 < j1);
            ko[i] = A ? j0 : j1;
            if (A) ia++; else ib++;
        }
    }
}

// host-side smem size
static inline int knn_smem(int padk){
    int sz_a = 128*padk*2;
    return 6*sz_a + 512 + 1024 + 128*LDD2R*4;
}

// ---------------- uv precompute: v = x@Wa, u = x@(Wb - Wa) ----------------
template<int CIN>
__global__ __launch_bounds__(256) void uv_kernel(
    const float* __restrict__ x, int xs, const float* __restrict__ w,
    float* __restrict__ u, float* __restrict__ v)
{
    __shared__ float sW1[CIN*64];
    __shared__ float sW2[CIN*64];
    __shared__ float sx[4][CIN];
    const int tid = threadIdx.x;
    const int p = tid >> 6, c = tid & 63;
    for (int i = tid; i < CIN*64; i += 256){
        float a = w[i];
        sW1[i] = a;
        sW2[i] = w[CIN*64 + i] - a;
    }
    const int gp = blockIdx.x*4 + p;
    for (int i = c; i < CIN; i += 64) sx[p][i] = x[(size_t)gp*xs + i];
    __syncthreads();
    float uu = 0.f, vv = 0.f;
#pragma unroll
    for (int d = 0; d < CIN; d++){
        float xv = sx[p][d];
        vv = fmaf(xv, sW1[d*64 + c], vv);
        uu = fmaf(xv, sW2[d*64 + c], uu);
    }
    u[(size_t)gp*64 + c] = uu;
    v[(size_t)gp*64 + c] = vv;
}

// ---------------- 2-layer edgeconv tail ----------------
__global__ __launch_bounds__(256) void edge2_kernel(
    const float* __restrict__ u, const float* __restrict__ v,
    const int* __restrict__ knn, const float* __restrict__ w2,
    const float* __restrict__ pa, int ia, float* __restrict__ out)
{
    __shared__ float sh1[4][64];
    const int tid = threadIdx.x;
    const int p = tid >> 6, c = tid & 63;
    float wcol[64];
#pragma unroll
    for (int d = 0; d < 64; d++) wcol[d] = __ldg(&w2[d*64 + c]);
    const float a1 = pa[ia], a2 = pa[ia+1];
    const int gp = blockIdx.x*4 + p;
    const int b  = gp >> 13;
    const float* vb = v + (size_t)b*NN*64;
    const float ur = u[(size_t)gp*64 + c];
    const int* krow = knn + (size_t)gp*KNN;
    float maxv = -FLT_MAX;
#pragma unroll
    for (int kk = 0; kk < KNN; kk++){
        int j = krow[kk];
        float h = prelu_f(ur + vb[(size_t)j*64 + c], a1);
        __syncthreads();
        sh1[p][c] = h;
        __syncthreads();
        float acc = 0.f;
#pragma unroll
        for (int d = 0; d < 64; d += 4){
            float4 hv = *(const float4*)&sh1[p][d];
            acc = fmaf(hv.x, wcol[d+0], acc);
            acc = fmaf(hv.y, wcol[d+1], acc);
            acc = fmaf(hv.z, wcol[d+2], acc);
            acc = fmaf(hv.w, wcol[d+3], acc);
        }
        maxv = fmaxf(maxv, prelu_f(acc, a2));
    }
    out[(size_t)gp*64 + c] = maxv;
}

// ---------------- 1-layer edgeconv tail ----------------
__global__ __launch_bounds__(256) void edge1_kernel(
    const float* __restrict__ u, const float* __restrict__ v,
    const int* __restrict__ knn, const float* __restrict__ pa, int ia,
    float* __restrict__ out)
{
    const int tid = threadIdx.x;
    const int p = tid >> 6, c = tid & 63;
    const float a1 = pa[ia];
    const int gp = blockIdx.x*4 + p;
    const int b  = gp >> 13;
    const float* vb = v + (size_t)b*NN*64;
    const float ur = u[(size_t)gp*64 + c];
    const int* krow = knn + (size_t)gp*KNN;
    float maxv = -FLT_MAX;
#pragma unroll
    for (int kk = 0; kk < KNN; kk++){
        int j = krow[kk];
        maxv = fmaxf(maxv, prelu_f(ur + vb[(size_t)j*64 + c], a1));
    }
    out[(size_t)gp*64 + c] = maxv;
}

// ---------------- init x5max ----------------
__global__ void init_x5max_kernel(){
    int i = blockIdx.x*256 + threadIdx.x;
    if (i < BB*1024) g_x5max[i] = 0u;
}

// ---------------- HMMA bf16-split GEMM (validated R9) ----------------
template<int Kd, bool GATHER, bool COLMAX>
__global__ __launch_bounds__(256) void hmma_gemm_kernel(
    const float* __restrict__ A1, const float* __restrict__ A2, const float* __restrict__ A3,
    int lda, const float* __restrict__ W, int Nc,
    const float* __restrict__ bias, float* __restrict__ Cout, int ldc,
    const float* __restrict__ pa, int ia)
{
    constexpr int PADW = Kd + 8;
    constexpr int PADA = 24;
    constexpr int OFF_WH = 0;
    constexpr int OFF_WL = 64*PADW*2;
    constexpr int OFF_AH = 2*OFF_WL;
    constexpr int OFF_AL = OFF_AH + 128*PADA*2;
    constexpr int OFF_SMAX = OFF_AL + 128*PADA*2;

    extern __shared__ char smp[];
    const uint32_t sbase = smem_u32(smp);
    __nv_bfloat16* Wh = (__nv_bfloat16*)(smp + OFF_WH);
    __nv_bfloat16* Wl = (__nv_bfloat16*)(smp + OFF_WL);
    __nv_bfloat16* Ah = (__nv_bfloat16*)(smp + OFF_AH);
    __nv_bfloat16* Al = (__nv_bfloat16*)(smp + OFF_AL);
    float* smax = (float*)(smp + OFF_SMAX);

    const int tid = threadIdx.x;
    const int w   = tid >> 5;
    const int l   = tid & 31;
    const int col0 = blockIdx.x*64;
    const int row0 = blockIdx.y*128;
    const int b = row0 >> 13;
    const float slope = pa[ia];

    for (int idx = tid; idx < Kd*64; idx += 256){
        int k = idx >> 6, n = idx & 63;
        float f = W[(size_t)k*Nc + col0 + n];
        __nv_bfloat16 h = __float2bfloat16(f);
        Wh[n*PADW + k] = h;
        Wl[n*PADW + k] = __float2bfloat16(f - __bfloat162float(h));
    }

    const int lq  = l >> 3;
    const int lr  = l & 7;
    const int rowq = ((lq & 1) << 3) + lr;
    const int colq = (lq >> 1) << 3;

    const uint32_t aAh = sbase + OFF_AH + (uint32_t)((w*16 + rowq)*PADA + colq)*2;
    const uint32_t aAl = sbase + OFF_AL + (uint32_t)((w*16 + rowq)*PADA + colq)*2;

    float acc[8][4];
#pragma unroll
    for (int f = 0; f < 8; f++)
#pragma unroll
        for (int j = 0; j < 4; j++) acc[f][j] = 0.f;

#pragma unroll 2
    for (int chunk = 0; chunk < Kd/16; chunk++){
        __syncthreads();
        const int k0 = chunk*16;
        const float* src; int koff; int ld;
        if (GATHER){
            if (k0 < 64)      { src = A1; koff = k0;       }
            else if (k0 < 128){ src = A2; koff = k0 - 64;  }
            else              { src = A3; koff = k0 - 128; }
            ld = 64;
        } else { src = A1; koff = k0; ld = lda; }

        for (int it = tid; it < 512; it += 256){
            int row = it >> 2, kq = (it & 3)*4;
            float4 v = *(const float4*)&src[(size_t)(row0 + row)*ld + koff + kq];
            __nv_bfloat16 h0 = __float2bfloat16(v.x);
            __nv_bfloat16 h1 = __float2bfloat16(v.y);
            __nv_bfloat16 h2 = __float2bfloat16(v.z);
            __nv_bfloat16 h3 = __float2bfloat16(v.w);
            __nv_bfloat16* ph = &Ah[row*PADA + kq];
            __nv_bfloat16* pl = &Al[row*PADA + kq];
            ph[0]=h0; ph[1]=h1; ph[2]=h2; ph[3]=h3;
            pl[0]=__float2bfloat16(v.x - __bfloat162float(h0));
            pl[1]=__float2bfloat16(v.y - __bfloat162float(h1));
            pl[2]=__float2bfloat16(v.z - __bfloat162float(h2));
            pl[3]=__float2bfloat16(v.w - __bfloat162float(h3));
        }
        __syncthreads();

        uint32_t ah0, ah1, ah2, ah3, al0, al1, al2, al3;
        ldsm_x4(ah0, ah1, ah2, ah3, aAh);
        ldsm_x4(al0, al1, al2, al3, aAl);
#pragma unroll
        for (int p = 0; p < 4; p++){
            uint32_t roff = (uint32_t)((p*16 + rowq)*PADW + k0 + colq)*2;
            uint32_t bh0, bh1, bh2, bh3, bl0, bl1, bl2, bl3;
            ldsm_x4(bh0, bh1, bh2, bh3, sbase + OFF_WH + roff);
            ldsm_x4(bl0, bl1, bl2, bl3, sbase + OFF_WL + roff);
            float* c0 = acc[2*p];
            float* c1 = acc[2*p+1];
            mma16816(c0[0], c0[1], c0[2], c0[3], ah0, ah1, ah2, ah3, bh0, bh2);
            mma16816(c1[0], c1[1], c1[2], c1[3], ah0, ah1, ah2, ah3, bh1, bh3);
            mma16816(c0[0], c0[1], c0[2], c0[3], ah0, ah1, ah2, ah3, bl0, bl2);
            mma16816(c1[0], c1[1], c1[2], c1[3], ah0, ah1, ah2, ah3, bl1, bl3);
            mma16816(c0[0], c0[1], c0[2], c0[3], al0, al1, al2, al3, bh0, bh2);
            mma16816(c1[0], c1[1], c1[2], c1[3], al0, al1, al2, al3, bh1, bh3);
        }
    }

    if (!COLMAX){
        const int r0 = w*16 + (l >> 2);
#pragma unroll
        for (int p = 0; p < 4; p++){
#pragma unroll
            for (int j = 0; j < 2; j++){
                const float* cc = acc[2*p + j];
                int col = p*16 + j*8 + (l & 3)*2;
                float b0 = bias ? bias[b*Nc + col0 + col]     : 0.f;
                float b1 = bias ? bias[b*Nc + col0 + col + 1] : 0.f;
                *(float2*)&Cout[(size_t)(row0 + r0)*ldc + col0 + col] =
                    make_float2(prelu_f(cc[0] + b0, slope), prelu_f(cc[1] + b1, slope));
                *(float2*)&Cout[(size_t)(row0 + r0 + 8)*ldc + col0 + col] =
                    make_float2(prelu_f(cc[2] + b0, slope), prelu_f(cc[3] + b1, slope));
            }
        }
    } else {
#pragma unroll
        for (int p = 0; p < 4; p++){
#pragma unroll
            for (int j = 0; j < 2; j++){
                const float* cc = acc[2*p + j];
                float m0 = fmaxf(cc[0], cc[2]);
                float m1 = fmaxf(cc[1], cc[3]);
#pragma unroll
                for (int s = 4; s <= 16; s <<= 1){
                    m0 = fmaxf(m0, __shfl_xor_sync(0xffffffffu, m0, s));
                    m1 = fmaxf(m1, __shfl_xor_sync(0xffffffffu, m1, s));
                }
                if (l < 4){
                    int col = p*16 + j*8 + l*2;
                    smax[w*64 + col]     = m0;
                    smax[w*64 + col + 1] = m1;
                }
            }
        }
        __syncthreads();
        if (tid < 64){
            float mm = smax[tid];
#pragma unroll
            for (int t = 1; t < 8; t++) mm = fmaxf(mm, smax[t*64 + tid]);
            atomicMax(&g_x5max[b*1024 + col0 + tid], enc_f(prelu_f(mm, slope)));
        }
    }
}

static inline int hg_smem(int Kd){
    int padw = Kd + 8;
    return 2*(64*padw*2) + 2*(128*24*2) + 8*64*4;
}

// ---------------- bias7 ----------------
__global__ __launch_bounds__(256) void bias7_kernel(const float* __restrict__ w7){
    int b = blockIdx.x, c = threadIdx.x;
    float acc = 0.f;
    for (int d = 0; d < 1024; d++){
        float v = dec_f(g_x5max[b*1024 + d]);
        acc = fmaf(v, w7[(size_t)(192 + d)*256 + c], acc);
    }
    g_bias7[b*256 + c] = acc;
}

// ---------------- final layer ----------------
__global__ __launch_bounds__(256) void head_out_kernel(
    const float* __restrict__ yc, const float* __restrict__ w10,
    const float* __restrict__ pa, float* __restrict__ out)
{
    __shared__ float sw[256];
    if (threadIdx.x < 256) sw[threadIdx.x] = w10[threadIdx.x];
    __syncthreads();
    const float slope = pa[9];
    const int row = blockIdx.x*256 + threadIdx.x;
    const float* yr = yc + (size_t)row*128;
    float a0 = 0.f, a1 = 0.f;
#pragma unroll
    for (int d = 0; d < 128; d++){
        float v = yr[d];
        a0 = fmaf(v, sw[2*d + 0], a0);
        a1 = fmaf(v, sw[2*d + 1], a1);
    }
    out[row*2 + 0] = prelu_f(a0, slope);
    out[row*2 + 1] = prelu_f(a1, slope);
}

// ---------------- host orchestration ----------------
extern "C" void kernel_launch(void* const* d_in, const int* in_sizes, int n_in,
                              void* d_out, int out_size)
{
    (void)in_sizes; (void)n_in; (void)out_size;
    const float* targets = (const float*)d_in[0];
    const float* w[10];
    for (int i = 0; i < 10; i++) w[i] = (const float*)d_in[1 + i];
    const float* pa = (const float*)d_in[11];
    float* out = (float*)d_out;

    void *px0, *px1, *px2, *px3, *pu, *pv, *pn, *pknn, *pya, *pyb, *pb7, *pbh, *pbl;
    cudaGetSymbolAddress(&px0, g_x0p);
    cudaGetSymbolAddress(&px1, g_x1);
    cudaGetSymbolAddress(&px2, g_x2);
    cudaGetSymbolAddress(&px3, g_x3);
    cudaGetSymbolAddress(&pu,  g_u);
    cudaGetSymbolAddress(&pv,  g_v);
    cudaGetSymbolAddress(&pn,  g_nrm);
    cudaGetSymbolAddress(&pknn, g_knn);
    cudaGetSymbolAddress(&pya, g_ya);
    cudaGetSymbolAddress(&pyb, g_yb);
    cudaGetSymbolAddress(&pb7, g_bias7);
    cudaGetSymbolAddress(&pbh, g_bh);
    cudaGetSymbolAddress(&pbl, g_bl);

    float* x0 = (float*)px0; float* x1 = (float*)px1;
    float* x2 = (float*)px2; float* x3 = (float*)px3;
    float* uu = (float*)pu;  float* vv = (float*)pv;
    float* nr = (float*)pn;
    int*   kn = (int*)pknn;
    float* ya = (float*)pya; float* yb = (float*)pyb;
    float* b7 = (float*)pb7;
    __nv_bfloat16* bh = (__nv_bfloat16*)pbh;
    __nv_bfloat16* bl = (__nv_bfloat16*)pbl;

    const int SMK1 = knn_smem(24);
    const int SMK4 = knn_smem(72);
    cudaFuncSetAttribute(knn_hmma_kernel<1,24>, cudaFuncAttributeMaxDynamicSharedMemorySize, SMK1);
    cudaFuncSetAttribute(knn_hmma_kernel<4,72>, cudaFuncAttributeMaxDynamicSharedMemorySize, SMK4);
    cudaFuncSetAttribute(hmma_gemm_kernel<192,true,true>,   cudaFuncAttributeMaxDynamicSharedMemorySize, hg_smem(192));
    cudaFuncSetAttribute(hmma_gemm_kernel<192,true,false>,  cudaFuncAttributeMaxDynamicSharedMemorySize, hg_smem(192));
    cudaFuncSetAttribute(hmma_gemm_kernel<256,false,false>, cudaFuncAttributeMaxDynamicSharedMemorySize, hg_smem(256));

    dim3 kgrid(NN/128, BB);

    // stage 0
    build_x0p_kernel<<<MTOT/256, 256>>>(targets);

    // stage 1: HMMA kNN on raw targets (C=3 padded to 16; distances = 0.5x ref -> same order)
    split3_kernel<<<MTOT/256, 256>>>(targets);
    knn_hmma_kernel<1,24><<<kgrid, 256, SMK1>>>(bh, bl, nr, kn);
    uv_kernel<6><<<MTOT/4, 256>>>(x0, 8, w[0], uu, vv);
    edge2_kernel<<<MTOT/4, 256>>>(uu, vv, kn, w[1], pa, 0, x1);

    // stage 2: HMMA kNN on x1
    norms64_kernel<<<MTOT/256, 256>>>(x1, nr);
    split_kernel<<<MTOT*64/256, 256>>>(x1);
    knn_hmma_kernel<4,72><<<kgrid, 256, SMK4>>>(bh, bl, nr, kn);
    uv_kernel<64><<<MTOT/4, 256>>>(x1, 64, w[2], uu, vv);
    edge2_kernel<<<MTOT/4, 256>>>(uu, vv, kn, w[3], pa, 2, x2);

    // stage 3: HMMA kNN on x2
    norms64_kernel<<<MTOT/256, 256>>>(x2, nr);
    split_kernel<<<MTOT*64/256, 256>>>(x2);
    knn_hmma_kernel<4,72><<<kgrid, 256, SMK4>>>(bh, bl, nr, kn);
    uv_kernel<64><<<MTOT/4, 256>>>(x2, 64, w[4], uu, vv);
    edge1_kernel<<<MTOT/4, 256>>>(uu, vv, kn, pa, 4, x3);

    // head (all HMMA)
    init_x5max_kernel<<<(BB*1024 + 255)/256, 256>>>();
    hmma_gemm_kernel<192,true,true><<<dim3(1024/64, MTOT/128), 256, hg_smem(192)>>>(
        x1, x2, x3, 64, w[5], 1024, nullptr, nullptr, 0, pa, 5);
    bias7_kernel<<<BB, 256>>>(w[6]);
    hmma_gemm_kernel<192,true,false><<<dim3(256/64, MTOT/128), 256, hg_smem(192)>>>(
        x1, x2, x3, 64, w[6], 256, b7, ya, 256, pa, 6);
    hmma_gemm_kernel<256,false,false><<<dim3(256/64, MTOT/128), 256, hg_smem(256)>>>(
        ya, nullptr, nullptr, 256, w[7], 256, nullptr, yb, 256, pa, 7);
    hmma_gemm_kernel<256,false,false><<<dim3(128/64, MTOT/128), 256, hg_smem(256)>>>(
        yb, nullptr, nullptr, 256, w[8], 128, nullptr, ya, 128, pa, 8);
    head_out_kernel<<<MTOT/256, 256>>>(ya, w[9], pa, out);
}